// round 1
// baseline (speedup 1.0000x reference)
#include <cuda_runtime.h>
#include <cstdint>

// Problem constants
#define BB 4
#define TT 1024
#define HH 16
#define DD 64
// out map size: B*T*H*T
#define MAPSZ 67108864u

// ---------------- scratch (device globals; no allocation allowed) ----------------
__device__ float g_phiq[BB * HH * TT * 128];   // [ (b*H+h)*T + t ][128]
__device__ float g_phik[BB * HH * TT * 128];

// ---------------- fast exp via FMA/ALU pipes (avoid MUFU.EX2 throughput wall) ----
__device__ __forceinline__ float fexp(float x) {
    float t  = x * 1.4426950408889634f;        // x * log2(e)
    float fi = t + 12582912.0f;                // round-to-nearest via magic (1.5*2^23)
    int   n  = __float_as_int(fi) - 0x4B400000;
    float f  = t - (fi - 12582912.0f);         // f in [-0.5, 0.5]
    float p  = 1.54035304e-4f;                 // ln2^6/720
    p = fmaf(p, f, 1.33335581e-3f);
    p = fmaf(p, f, 9.61812911e-3f);
    p = fmaf(p, f, 5.55041087e-2f);
    p = fmaf(p, f, 2.40226507e-1f);
    p = fmaf(p, f, 6.93147181e-1f);
    p = fmaf(p, f, 1.0f);
    return __int_as_float(__float_as_int(p) + (n << 23));
}

// ---------------- packed fp32x2 helpers ----------------
__device__ __forceinline__ void fma2(unsigned long long& acc,
                                     unsigned long long a, unsigned long long b) {
    asm volatile("fma.rn.f32x2 %0, %1, %2, %0;" : "+l"(acc) : "l"(a), "l"(b));
}
__device__ __forceinline__ void unpack2(unsigned long long v, float& lo, float& hi) {
    asm("mov.b64 {%0, %1}, %2;" : "=f"(lo), "=f"(hi) : "l"(v));
}

// =====================================================================
// Kernel 1: feature maps  phi = [exp(y), exp(-y)],  y = x @ W^T + b
// grid = B*T blocks, 256 threads. Each block: all 16 heads, both q and k.
// =====================================================================
__global__ __launch_bounds__(256) void hedgehog_prep(
    const float* __restrict__ q, const float* __restrict__ k,
    const float* __restrict__ Wq, const float* __restrict__ bq,
    const float* __restrict__ Wk, const float* __restrict__ bk)
{
    __shared__ float wt[2][64 * 64];   // W transposed into d-pair layout:
                                       // wt[(dp*64+e)*2 + par] = W[e][2*dp+par]
    __shared__ float xs[2][16 * 64];   // xs[tensor][h*64 + d]
    __shared__ float bias[2][64];

    const int tid = threadIdx.x;
    const int bi  = blockIdx.x;
    const int b   = bi >> 10;
    const int t   = bi & 1023;

    // Load W (coalesced along d) into transposed-pair layout
    {
        const int d = tid & 63;
        const int e0 = tid >> 6;          // 0..3
        #pragma unroll
        for (int e = e0; e < 64; e += 4) {
            int wi = ((d >> 1) * 64 + e) * 2 + (d & 1);
            wt[0][wi] = Wq[e * 64 + d];
            wt[1][wi] = Wk[e * 64 + d];
        }
        if (tid < 64) { bias[0][tid] = bq[tid]; bias[1][tid] = bk[tid]; }
    }
    // Load x rows for all heads
    {
        const size_t base = (size_t)(b * 1024 + t) * (16 * 64);
        #pragma unroll
        for (int i = tid; i < 1024; i += 256) {
            xs[0][i] = q[base + i];
            xs[1][i] = k[base + i];
        }
    }
    __syncthreads();

    const int e      = tid & 63;
    const int grp    = tid >> 6;       // 0..3
    const int tensor = grp >> 1;       // 0 = q, 1 = k
    const int hbase  = (grp & 1) * 8;

    float y[8];
    #pragma unroll
    for (int c = 0; c < 8; ++c) y[c] = bias[tensor][e];

    const float2* w2 = reinterpret_cast<const float2*>(wt[tensor]);
    const float2* x2 = reinterpret_cast<const float2*>(xs[tensor]);
    #pragma unroll 8
    for (int dp = 0; dp < 32; ++dp) {
        float2 w = w2[dp * 64 + e];
        #pragma unroll
        for (int c = 0; c < 8; ++c) {
            float2 xv = x2[(hbase + c) * 32 + dp];
            y[c] = fmaf(w.x, xv.x, y[c]);
            y[c] = fmaf(w.y, xv.y, y[c]);
        }
    }

    float* dst = tensor ? g_phik : g_phiq;
    #pragma unroll
    for (int c = 0; c < 8; ++c) {
        const int h = hbase + c;
        const size_t row = ((size_t)(b * 16 + h) * 1024 + t) * 128;
        dst[row + e]      = fexp(y[c]);
        dst[row + 64 + e] = fexp(-y[c]);
    }
}

// =====================================================================
// Kernel 2: fused attention maps.
// Block = (qtile of 128 rows, one (b,h)). 256 threads, 8x8 per-thread tile,
// fp32x2 d-pair packed accumulators. Two GEMM phases per k-tile (scores + phi),
// row sums accumulated in registers, then in-block normalization over the
// block's own (L2-hot) output.
// =====================================================================
#define SA 66      // smem row stride (floats) for 64-wide tiles
#define SB 130     // smem row stride (floats) for 128-wide tiles
#define SMEM_FLOATS (2*128*SA + 2*128*SB)   // 50176 floats = 200704 B

__device__ __forceinline__ void load_tile64(float* dst, const float* src, int srcStride) {
    const int tid = threadIdx.x;
    const int qtr = tid & 3;
    const int r0  = tid >> 2;
    #pragma unroll
    for (int pass = 0; pass < 2; ++pass) {
        const int r = r0 + pass * 64;
        const float4* s = reinterpret_cast<const float4*>(src + (size_t)r * srcStride + qtr * 16);
        float* d = dst + r * SA + qtr * 16;
        #pragma unroll
        for (int i = 0; i < 4; ++i) {
            float4 v = s[i];
            reinterpret_cast<float2*>(d)[i * 2]     = make_float2(v.x, v.y);
            reinterpret_cast<float2*>(d)[i * 2 + 1] = make_float2(v.z, v.w);
        }
    }
}

__device__ __forceinline__ void load_tile128(float* dst, const float* src) {
    const int tid = threadIdx.x;
    const int qtr = tid & 3;
    const int r0  = tid >> 2;
    #pragma unroll
    for (int pass = 0; pass < 2; ++pass) {
        const int r = r0 + pass * 64;
        const float4* s = reinterpret_cast<const float4*>(src + (size_t)r * 128 + qtr * 32);
        float* d = dst + r * SB + qtr * 32;
        #pragma unroll
        for (int i = 0; i < 8; ++i) {
            float4 v = s[i];
            reinterpret_cast<float2*>(d)[i * 2]     = make_float2(v.x, v.y);
            reinterpret_cast<float2*>(d)[i * 2 + 1] = make_float2(v.z, v.w);
        }
    }
}

__global__ __launch_bounds__(256, 1) void hedgehog_main(
    const float* __restrict__ q, const float* __restrict__ k, float* __restrict__ out)
{
    extern __shared__ float sm[];
    float* Qs = sm;                      // [128][SA]
    float* Ks = sm + 128 * SA;           // [128][SA]
    float* Pq = sm + 2 * 128 * SA;       // [128][SB]
    float* Pk = Pq + 128 * SB;           // [128][SB]

    const int tid = threadIdx.x;
    const int tx  = tid & 15;
    const int ty  = tid >> 4;
    const int qt  = blockIdx.x;          // 0..7
    const int bh  = blockIdx.y;          // 0..63
    const int b   = bh >> 4;
    const int h   = bh & 15;
    const int t0  = qt * 128;

    const size_t xbase = ((size_t)b * 1024 * 16 + h) * 64;       // q/k element base
    const size_t pbase = (size_t)(b * 16 + h) * 1024 * 128;      // phi base

    load_tile64 (Qs, q + xbase + (size_t)t0 * 1024, 1024);
    load_tile128(Pq, g_phiq + pbase + (size_t)t0 * 128);

    unsigned long long acc[64];
    float rsum1[8], rsum2[8];
    #pragma unroll
    for (int i = 0; i < 8; ++i) { rsum1[i] = 0.f; rsum2[i] = 0.f; }

    unsigned int rowb[8];
    #pragma unroll
    for (int i = 0; i < 8; ++i)
        rowb[i] = ((unsigned)(b * 1024 + t0 + ty * 8 + i) * 16 + h) * 1024 + tx;

    const unsigned long long* Aq = reinterpret_cast<const unsigned long long*>(Qs);
    const unsigned long long* Bk = reinterpret_cast<const unsigned long long*>(Ks);
    const unsigned long long* Ap = reinterpret_cast<const unsigned long long*>(Pq);
    const unsigned long long* Bp = reinterpret_cast<const unsigned long long*>(Pk);

    for (int kt = 0; kt < 8; ++kt) {
        __syncthreads();
        load_tile64 (Ks, k + xbase + (size_t)(kt * 128) * 1024, 1024);
        load_tile128(Pk, g_phik + pbase + (size_t)(kt * 128) * 128);
        __syncthreads();

        // ---- Phase A: scores = q . k^T (inner 64, as 32 d-pairs) ----
        #pragma unroll
        for (int n = 0; n < 64; ++n) acc[n] = 0ull;
        #pragma unroll 4
        for (int dp = 0; dp < 32; ++dp) {
            unsigned long long av[8], bv[8];
            #pragma unroll
            for (int i = 0; i < 8; ++i) av[i] = Aq[(ty * 8 + i) * 33 + dp];
            #pragma unroll
            for (int j = 0; j < 8; ++j) bv[j] = Bk[(j * 16 + tx) * 33 + dp];
            #pragma unroll
            for (int i = 0; i < 8; ++i)
                #pragma unroll
                for (int j = 0; j < 8; ++j)
                    fma2(acc[i * 8 + j], av[i], bv[j]);
        }
        {
            const unsigned colb = (unsigned)(kt * 128);
            #pragma unroll
            for (int i = 0; i < 8; ++i) {
                #pragma unroll
                for (int j = 0; j < 8; ++j) {
                    float lo, hi; unpack2(acc[i * 8 + j], lo, hi);
                    float p = fexp((lo + hi) * 0.125f);   // scale = 1/sqrt(64)
                    rsum1[i] += p;
                    out[rowb[i] + colb + j * 16] = p;     // unnormalized
                }
            }
        }

        // ---- Phase B: phi_q . phi_k^T (inner 128, as 64 e-pairs) ----
        #pragma unroll
        for (int n = 0; n < 64; ++n) acc[n] = 0ull;
        #pragma unroll 4
        for (int ep = 0; ep < 64; ++ep) {
            unsigned long long av[8], bv[8];
            #pragma unroll
            for (int i = 0; i < 8; ++i) av[i] = Ap[(ty * 8 + i) * 65 + ep];
            #pragma unroll
            for (int j = 0; j < 8; ++j) bv[j] = Bp[(j * 16 + tx) * 65 + ep];
            #pragma unroll
            for (int i = 0; i < 8; ++i)
                #pragma unroll
                for (int j = 0; j < 8; ++j)
                    fma2(acc[i * 8 + j], av[i], bv[j]);
        }
        {
            const unsigned colb = (unsigned)(kt * 128);
            #pragma unroll
            for (int i = 0; i < 8; ++i) {
                #pragma unroll
                for (int j = 0; j < 8; ++j) {
                    float lo, hi; unpack2(acc[i * 8 + j], lo, hi);
                    float v = lo + hi;
                    rsum2[i] += v;
                    out[MAPSZ + rowb[i] + colb + j * 16] = v;  // unnormalized
                }
            }
        }
    }

    // ---- row-sum reduction across the 16 tx lanes (within half-warp groups) ----
    #pragma unroll
    for (int i = 0; i < 8; ++i) {
        #pragma unroll
        for (int m = 1; m < 16; m <<= 1) {
            rsum1[i] += __shfl_xor_sync(0xffffffffu, rsum1[i], m);
            rsum2[i] += __shfl_xor_sync(0xffffffffu, rsum2[i], m);
        }
    }
    __syncthreads();
    float* rs = sm;  // reuse Qs region
    if (tx == 0) {
        #pragma unroll
        for (int i = 0; i < 8; ++i) {
            rs[ty * 8 + i]       = 1.0f / rsum1[i];
            rs[128 + ty * 8 + i] = 1.0f / rsum2[i];
        }
    }
    __syncthreads();

    // ---- in-block normalization over this block's own (L2-hot) output ----
    const size_t blockbase = ((size_t)(b * 1024 + t0) * 16 + h) * 1024;
    #pragma unroll 4
    for (int idx = tid; idx < 2 * 128 * 256; idx += 256) {
        const int m  = idx >> 15;
        const int r  = (idx >> 8) & 127;
        const int c4 = idx & 255;
        const float s = rs[m * 128 + r];
        float4* p = reinterpret_cast<float4*>(out + (size_t)m * MAPSZ + blockbase
                                              + (size_t)r * 16384) + c4;
        float4 v = *p;
        v.x *= s; v.y *= s; v.z *= s; v.w *= s;
        *p = v;
    }
}

// =====================================================================
extern "C" void kernel_launch(void* const* d_in, const int* in_sizes, int n_in,
                              void* d_out, int out_size) {
    const float* q  = (const float*)d_in[0];
    const float* k  = (const float*)d_in[1];
    const float* Wq = (const float*)d_in[2];
    const float* bq = (const float*)d_in[3];
    const float* Wk = (const float*)d_in[4];
    const float* bk = (const float*)d_in[5];
    float* out = (float*)d_out;

    const int smemBytes = SMEM_FLOATS * (int)sizeof(float);  // 200704 B
    cudaFuncSetAttribute(hedgehog_main, cudaFuncAttributeMaxDynamicSharedMemorySize, smemBytes);

    hedgehog_prep<<<BB * TT, 256>>>(q, k, Wq, bq, Wk, bk);
    hedgehog_main<<<dim3(TT / 128, BB * HH), 256, smemBytes>>>(q, k, out);
}

// round 2
// speedup vs baseline: 1.3155x; 1.3155x over previous
#include <cuda_runtime.h>
#include <cstdint>

#define BB 4
#define TT 1024
#define HH 16
#define DD 64
#define MAPSZ 67108864u

// ---------------- scratch (device globals) ----------------
__device__ float g_phiq[BB * HH * TT * 128];
__device__ float g_phik[BB * HH * TT * 128];
__device__ float g_sk[BB * HH * 128];          // sum over T of phi_k, per (b,h)

// ---------------- fast exp on FMA/ALU pipes ----------------
__device__ __forceinline__ float fexp(float x) {
    float t  = x * 1.4426950408889634f;
    float fi = t + 12582912.0f;
    int   n  = __float_as_int(fi) - 0x4B400000;
    float f  = t - (fi - 12582912.0f);
    float p  = 1.54035304e-4f;
    p = fmaf(p, f, 1.33335581e-3f);
    p = fmaf(p, f, 9.61812911e-3f);
    p = fmaf(p, f, 5.55041087e-2f);
    p = fmaf(p, f, 2.40226507e-1f);
    p = fmaf(p, f, 6.93147181e-1f);
    p = fmaf(p, f, 1.0f);
    return __int_as_float(__float_as_int(p) + (n << 23));
}

// ---------------- packed fp32x2 helpers ----------------
__device__ __forceinline__ void fma2(unsigned long long& acc,
                                     unsigned long long a, unsigned long long b) {
    asm volatile("fma.rn.f32x2 %0, %1, %2, %0;" : "+l"(acc) : "l"(a), "l"(b));
}
__device__ __forceinline__ void unpack2(unsigned long long v, float& lo, float& hi) {
    asm("mov.b64 {%0, %1}, %2;" : "=f"(lo), "=f"(hi) : "l"(v));
}

// ---------------- cp.async 8B ----------------
__device__ __forceinline__ void cp8(float* dst_smem, const float* src) {
    unsigned int a = (unsigned int)__cvta_generic_to_shared(dst_smem);
    asm volatile("cp.async.ca.shared.global [%0], [%1], 8;" :: "r"(a), "l"(src));
}
__device__ __forceinline__ void cp_commit() {
    asm volatile("cp.async.commit_group;");
}
template<int N> __device__ __forceinline__ void cp_wait() {
    asm volatile("cp.async.wait_group %0;" :: "n"(N));
}

// =====================================================================
// Kernel 1: feature maps  phi = [exp(y), exp(-y)],  y = x @ W^T + b
// =====================================================================
__global__ __launch_bounds__(256) void hedgehog_prep(
    const float* __restrict__ q, const float* __restrict__ k,
    const float* __restrict__ Wq, const float* __restrict__ bq,
    const float* __restrict__ Wk, const float* __restrict__ bk)
{
    __shared__ float wt[2][64 * 64];
    __shared__ float xs[2][16 * 64];
    __shared__ float bias[2][64];

    const int tid = threadIdx.x;
    const int bi  = blockIdx.x;
    const int b   = bi >> 10;
    const int t   = bi & 1023;

    {
        const int d = tid & 63;
        const int e0 = tid >> 6;
        #pragma unroll
        for (int e = e0; e < 64; e += 4) {
            int wi = ((d >> 1) * 64 + e) * 2 + (d & 1);
            wt[0][wi] = Wq[e * 64 + d];
            wt[1][wi] = Wk[e * 64 + d];
        }
        if (tid < 64) { bias[0][tid] = bq[tid]; bias[1][tid] = bk[tid]; }
    }
    {
        const size_t base = (size_t)(b * 1024 + t) * (16 * 64);
        #pragma unroll
        for (int i = tid; i < 1024; i += 256) {
            xs[0][i] = q[base + i];
            xs[1][i] = k[base + i];
        }
    }
    __syncthreads();

    const int e      = tid & 63;
    const int grp    = tid >> 6;
    const int tensor = grp >> 1;
    const int hbase  = (grp & 1) * 8;

    float y[8];
    #pragma unroll
    for (int c = 0; c < 8; ++c) y[c] = bias[tensor][e];

    const float2* w2 = reinterpret_cast<const float2*>(wt[tensor]);
    const float2* x2 = reinterpret_cast<const float2*>(xs[tensor]);
    #pragma unroll 8
    for (int dp = 0; dp < 32; ++dp) {
        float2 w = w2[dp * 64 + e];
        #pragma unroll
        for (int c = 0; c < 8; ++c) {
            float2 xv = x2[(hbase + c) * 32 + dp];
            y[c] = fmaf(w.x, xv.x, y[c]);
            y[c] = fmaf(w.y, xv.y, y[c]);
        }
    }

    float* dst = tensor ? g_phik : g_phiq;
    #pragma unroll
    for (int c = 0; c < 8; ++c) {
        const int h = hbase + c;
        const size_t row = ((size_t)(b * 16 + h) * 1024 + t) * 128;
        dst[row + e]      = fexp(y[c]);
        dst[row + 64 + e] = fexp(-y[c]);
    }
}

// =====================================================================
// Kernel 1b: S_k[bh][e] = sum_t phi_k[bh][t][e]
// =====================================================================
__global__ __launch_bounds__(128) void hedgehog_ksum()
{
    const int bh = blockIdx.x;
    const int e  = threadIdx.x;
    const float* src = g_phik + (size_t)bh * 1024 * 128 + e;
    float s = 0.f;
    #pragma unroll 8
    for (int t = 0; t < 1024; ++t) s += src[(size_t)t * 128];
    g_sk[bh * 128 + e] = s;
}

// =====================================================================
// Kernel 2: fused attention maps, cp.async double-buffered, 64-wide k tiles.
// Block: 128 q-rows x one (b,h). 256 threads, per-thread 8x4 packed-fp32x2.
// Map2 written normalized directly (denominator via S_k). Map1 RMW-normalized
// in-block (L2-hot).
// =====================================================================
#define SA 66
#define SB 130
// smem floats: Qs 128*66=8448, Pq 128*130=16640, Ks 2*64*66=8448,
// Pk 2*64*130=16640, norm 256  -> 50432 floats = 201728 B
#define QS_OFF   0
#define PQ_OFF   8448
#define KS_OFF   25088
#define PK_OFF   33536
#define NORM_OFF 50176
#define SMEM_FLOATS 50432

__global__ __launch_bounds__(256, 1) void hedgehog_main(
    const float* __restrict__ q, const float* __restrict__ k, float* __restrict__ out)
{
    extern __shared__ float sm[];
    float* Qs   = sm + QS_OFF;
    float* Pq   = sm + PQ_OFF;
    float* inv2 = sm + NORM_OFF;          // [128]
    float* rs   = sm + NORM_OFF + 128;    // [128]

    const int tid = threadIdx.x;
    const int tx  = tid & 15;
    const int ty  = tid >> 4;
    const int qt  = blockIdx.x;
    const int bh  = blockIdx.y;
    const int b   = bh >> 4;
    const int h   = bh & 15;
    const int t0  = qt * 128;

    const float* qbase = q + ((size_t)b * 1024 * 16 + h) * 64;   // +t*1024
    const float* kbase = k + ((size_t)b * 1024 * 16 + h) * 64;
    const float* pqb   = g_phiq + (size_t)bh * 1024 * 128;
    const float* pkb   = g_phik + (size_t)bh * 1024 * 128;

    // ---- prologue: async load Qs, Pq, Ks[0], Pk[0] (group 0) ----
    {
        // Qs: 128 rows x 64 floats = 4096 8B-chunks
        #pragma unroll
        for (int p = 0; p < 16; ++p) {
            int idx = p * 256 + tid;
            int r = idx >> 5, c = idx & 31;
            cp8(Qs + r * SA + c * 2, qbase + (size_t)(t0 + r) * 1024 + c * 2);
        }
        // Pq: 128 rows x 128 floats = 8192 chunks
        #pragma unroll
        for (int p = 0; p < 32; ++p) {
            int idx = p * 256 + tid;
            int r = idx >> 6, c = idx & 63;
            cp8(Pq + r * SB + c * 2, pqb + (size_t)(t0 + r) * 128 + c * 2);
        }
        // Ks[0]: 64 x 64 = 2048 chunks
        #pragma unroll
        for (int p = 0; p < 8; ++p) {
            int idx = p * 256 + tid;
            int r = idx >> 5, c = idx & 31;
            cp8(sm + KS_OFF + r * SA + c * 2, kbase + (size_t)r * 1024 + c * 2);
        }
        // Pk[0]: 64 x 128 = 4096 chunks
        #pragma unroll
        for (int p = 0; p < 16; ++p) {
            int idx = p * 256 + tid;
            int r = idx >> 6, c = idx & 63;
            cp8(sm + PK_OFF + r * SB + c * 2, pkb + (size_t)r * 128 + c * 2);
        }
        cp_commit();
    }

    unsigned long long acc[32];
    float rsum1[8];
    #pragma unroll
    for (int i = 0; i < 8; ++i) rsum1[i] = 0.f;

    unsigned int rowb[8];
    #pragma unroll
    for (int i = 0; i < 8; ++i)
        rowb[i] = ((unsigned)(b * 1024 + t0 + ty * 8 + i) * 16 + h) * 1024 + tx;

    const unsigned long long* Aq = reinterpret_cast<const unsigned long long*>(Qs);
    const unsigned long long* Ap = reinterpret_cast<const unsigned long long*>(Pq);

    for (int kt = 0; kt < 16; ++kt) {
        const int cur = kt & 1;
        // issue next tile's loads (buffer was last used at kt-1; trailing barrier
        // of kt-1 protects it)
        if (kt < 15) {
            const int nb = (kt + 1) & 1;
            const int kr = (kt + 1) * 64;
            #pragma unroll
            for (int p = 0; p < 8; ++p) {
                int idx = p * 256 + tid;
                int r = idx >> 5, c = idx & 31;
                cp8(sm + KS_OFF + nb * (64 * SA) + r * SA + c * 2,
                    kbase + (size_t)(kr + r) * 1024 + c * 2);
            }
            #pragma unroll
            for (int p = 0; p < 16; ++p) {
                int idx = p * 256 + tid;
                int r = idx >> 6, c = idx & 63;
                cp8(sm + PK_OFF + nb * (64 * SB) + r * SB + c * 2,
                    pkb + (size_t)(kr + r) * 128 + c * 2);
            }
            cp_commit();
            cp_wait<1>();
        } else {
            cp_wait<0>();
        }
        __syncthreads();

        if (kt == 0) {
            // denominators for map2: inv2[r] = 1 / (Pq[r] . S_k)
            if (tid < 128) {
                const float* skp = g_sk + bh * 128;
                const float* pr  = Pq + tid * SB;
                float s = 0.f;
                #pragma unroll 8
                for (int e = 0; e < 128; ++e) s = fmaf(pr[e], skp[e], s);
                inv2[tid] = 1.0f / s;
            }
            __syncthreads();
        }

        const unsigned long long* Bk =
            reinterpret_cast<const unsigned long long*>(sm + KS_OFF + cur * (64 * SA));
        const unsigned long long* Bp =
            reinterpret_cast<const unsigned long long*>(sm + PK_OFF + cur * (64 * SB));

        // ---- Phase A: scores (inner 64 -> 32 packed pairs) ----
        #pragma unroll
        for (int n = 0; n < 32; ++n) acc[n] = 0ull;
        #pragma unroll 4
        for (int dp = 0; dp < 32; ++dp) {
            unsigned long long av[8], bv[4];
            #pragma unroll
            for (int i = 0; i < 8; ++i) av[i] = Aq[(ty * 8 + i) * 33 + dp];
            #pragma unroll
            for (int j = 0; j < 4; ++j) bv[j] = Bk[(j * 16 + tx) * 33 + dp];
            #pragma unroll
            for (int i = 0; i < 8; ++i)
                #pragma unroll
                for (int j = 0; j < 4; ++j)
                    fma2(acc[i * 4 + j], av[i], bv[j]);
        }
        {
            const unsigned colb = (unsigned)(kt * 64);
            #pragma unroll
            for (int i = 0; i < 8; ++i) {
                #pragma unroll
                for (int j = 0; j < 4; ++j) {
                    float lo, hi; unpack2(acc[i * 4 + j], lo, hi);
                    float p = fexp((lo + hi) * 0.125f);
                    rsum1[i] += p;
                    out[rowb[i] + colb + j * 16] = p;           // unnormalized
                }
            }
        }

        // ---- Phase B: phi_q . phi_k^T (inner 128 -> 64 packed pairs) ----
        #pragma unroll
        for (int n = 0; n < 32; ++n) acc[n] = 0ull;
        #pragma unroll 4
        for (int ep = 0; ep < 64; ++ep) {
            unsigned long long av[8], bv[4];
            #pragma unroll
            for (int i = 0; i < 8; ++i) av[i] = Ap[(ty * 8 + i) * 65 + ep];
            #pragma unroll
            for (int j = 0; j < 4; ++j) bv[j] = Bp[(j * 16 + tx) * 65 + ep];
            #pragma unroll
            for (int i = 0; i < 8; ++i)
                #pragma unroll
                for (int j = 0; j < 4; ++j)
                    fma2(acc[i * 4 + j], av[i], bv[j]);
        }
        {
            const unsigned colb = (unsigned)(kt * 64);
            #pragma unroll
            for (int i = 0; i < 8; ++i) {
                const float s2 = inv2[ty * 8 + i];
                #pragma unroll
                for (int j = 0; j < 4; ++j) {
                    float lo, hi; unpack2(acc[i * 4 + j], lo, hi);
                    out[MAPSZ + rowb[i] + colb + j * 16] = (lo + hi) * s2;  // normalized
                }
            }
        }
        __syncthreads();   // protect buffers before next issue
    }

    // ---- map1 row-sum reduction across the 16 tx lanes ----
    #pragma unroll
    for (int i = 0; i < 8; ++i)
        #pragma unroll
        for (int m = 1; m < 16; m <<= 1)
            rsum1[i] += __shfl_xor_sync(0xffffffffu, rsum1[i], m);
    if (tx == 0) {
        #pragma unroll
        for (int i = 0; i < 8; ++i) rs[ty * 8 + i] = 1.0f / rsum1[i];
    }
    __syncthreads();

    // ---- map1 in-block normalization (L2-hot RMW) ----
    const size_t blockbase = ((size_t)(b * 1024 + t0) * 16 + h) * 1024;
    #pragma unroll 4
    for (int idx = tid; idx < 128 * 256; idx += 256) {
        const int r  = idx >> 8;
        const int c4 = idx & 255;
        const float s = rs[r];
        float4* p = reinterpret_cast<float4*>(out + blockbase + (size_t)r * 16384) + c4;
        float4 v = *p;
        v.x *= s; v.y *= s; v.z *= s; v.w *= s;
        *p = v;
    }
}

// =====================================================================
extern "C" void kernel_launch(void* const* d_in, const int* in_sizes, int n_in,
                              void* d_out, int out_size) {
    const float* q  = (const float*)d_in[0];
    const float* k  = (const float*)d_in[1];
    const float* Wq = (const float*)d_in[2];
    const float* bq = (const float*)d_in[3];
    const float* Wk = (const float*)d_in[4];
    const float* bk = (const float*)d_in[5];
    float* out = (float*)d_out;

    const int smemBytes = SMEM_FLOATS * (int)sizeof(float);
    cudaFuncSetAttribute(hedgehog_main, cudaFuncAttributeMaxDynamicSharedMemorySize, smemBytes);

    hedgehog_prep<<<BB * TT, 256>>>(q, k, Wq, bq, Wk, bk);
    hedgehog_ksum<<<BB * HH, 128>>>();
    hedgehog_main<<<dim3(TT / 128, BB * HH), 256, smemBytes>>>(q, k, out);
}

// round 3
// speedup vs baseline: 1.3163x; 1.0007x over previous
#include <cuda_runtime.h>
#include <cstdint>

#define BB 4
#define TT 1024
#define HH 16
#define DD 64
#define MAPSZ 67108864u

// ---------------- scratch (device globals) ----------------
__device__ float g_phiq[BB * HH * TT * 128];
__device__ float g_phik[BB * HH * TT * 128];
__device__ float g_sk[BB * HH * 128];          // sum over T of phi_k, per (b,h)

// ---------------- fast exp on FMA/ALU pipes ----------------
__device__ __forceinline__ float fexp(float x) {
    float t  = x * 1.4426950408889634f;
    float fi = t + 12582912.0f;
    int   n  = __float_as_int(fi) - 0x4B400000;
    float f  = t - (fi - 12582912.0f);
    float p  = 1.54035304e-4f;
    p = fmaf(p, f, 1.33335581e-3f);
    p = fmaf(p, f, 9.61812911e-3f);
    p = fmaf(p, f, 5.55041087e-2f);
    p = fmaf(p, f, 2.40226507e-1f);
    p = fmaf(p, f, 6.93147181e-1f);
    p = fmaf(p, f, 1.0f);
    return __int_as_float(__float_as_int(p) + (n << 23));
}

// ---------------- packed fp32x2 helpers ----------------
__device__ __forceinline__ void fma2(unsigned long long& acc,
                                     unsigned long long a, unsigned long long b) {
    asm volatile("fma.rn.f32x2 %0, %1, %2, %0;" : "+l"(acc) : "l"(a), "l"(b));
}
__device__ __forceinline__ void unpack2(unsigned long long v, float& lo, float& hi) {
    asm("mov.b64 {%0, %1}, %2;" : "=f"(lo), "=f"(hi) : "l"(v));
}

// ---------------- cp.async 8B ----------------
__device__ __forceinline__ void cp8(float* dst_smem, const float* src) {
    unsigned int a = (unsigned int)__cvta_generic_to_shared(dst_smem);
    asm volatile("cp.async.ca.shared.global [%0], [%1], 8;" :: "r"(a), "l"(src));
}
__device__ __forceinline__ void cp_commit() {
    asm volatile("cp.async.commit_group;");
}
template<int N> __device__ __forceinline__ void cp_wait() {
    asm volatile("cp.async.wait_group %0;" :: "n"(N));
}

// =====================================================================
// Kernel 1: feature maps  phi = [exp(y), exp(-y)],  y = x @ W^T + b
// =====================================================================
__global__ __launch_bounds__(256) void hedgehog_prep(
    const float* __restrict__ q, const float* __restrict__ k,
    const float* __restrict__ Wq, const float* __restrict__ bq,
    const float* __restrict__ Wk, const float* __restrict__ bk)
{
    __shared__ float wt[2][64 * 64];
    __shared__ float xs[2][16 * 64];
    __shared__ float bias[2][64];

    const int tid = threadIdx.x;
    const int bi  = blockIdx.x;
    const int b   = bi >> 10;
    const int t   = bi & 1023;

    {
        const int d = tid & 63;
        const int e0 = tid >> 6;
        #pragma unroll
        for (int e = e0; e < 64; e += 4) {
            int wi = ((d >> 1) * 64 + e) * 2 + (d & 1);
            wt[0][wi] = Wq[e * 64 + d];
            wt[1][wi] = Wk[e * 64 + d];
        }
        if (tid < 64) { bias[0][tid] = bq[tid]; bias[1][tid] = bk[tid]; }
    }
    {
        const size_t base = (size_t)(b * 1024 + t) * (16 * 64);
        #pragma unroll
        for (int i = tid; i < 1024; i += 256) {
            xs[0][i] = q[base + i];
            xs[1][i] = k[base + i];
        }
    }
    __syncthreads();

    const int e      = tid & 63;
    const int grp    = tid >> 6;
    const int tensor = grp >> 1;
    const int hbase  = (grp & 1) * 8;

    float y[8];
    #pragma unroll
    for (int c = 0; c < 8; ++c) y[c] = bias[tensor][e];

    const float2* w2 = reinterpret_cast<const float2*>(wt[tensor]);
    const float2* x2 = reinterpret_cast<const float2*>(xs[tensor]);
    #pragma unroll 8
    for (int dp = 0; dp < 32; ++dp) {
        float2 w = w2[dp * 64 + e];
        #pragma unroll
        for (int c = 0; c < 8; ++c) {
            float2 xv = x2[(hbase + c) * 32 + dp];
            y[c] = fmaf(w.x, xv.x, y[c]);
            y[c] = fmaf(w.y, xv.y, y[c]);
        }
    }

    float* dst = tensor ? g_phik : g_phiq;
    #pragma unroll
    for (int c = 0; c < 8; ++c) {
        const int h = hbase + c;
        const size_t row = ((size_t)(b * 16 + h) * 1024 + t) * 128;
        dst[row + e]      = fexp(y[c]);
        dst[row + 64 + e] = fexp(-y[c]);
    }
}

// =====================================================================
// Kernel 1b: S_k[bh][e] = sum_t phi_k[bh][t][e]
// =====================================================================
__global__ __launch_bounds__(128) void hedgehog_ksum()
{
    const int bh = blockIdx.x;
    const int e  = threadIdx.x;
    const float* src = g_phik + (size_t)bh * 1024 * 128 + e;
    float s = 0.f;
    #pragma unroll 8
    for (int t = 0; t < 1024; ++t) s += src[(size_t)t * 128];
    g_sk[bh * 128 + e] = s;
}

// =====================================================================
// Kernel 2: fused attention maps, cp.async double-buffered, 64-wide k tiles.
// Block: 128 q-rows x one (b,h). 256 threads, per-thread 8x4 packed-fp32x2.
// Map2 written normalized directly (denominator via S_k). Map1 RMW-normalized
// in-block (L2-hot).
// =====================================================================
#define SA 66
#define SB 130
// smem floats: Qs 128*66=8448, Pq 128*130=16640, Ks 2*64*66=8448,
// Pk 2*64*130=16640, norm 256  -> 50432 floats = 201728 B
#define QS_OFF   0
#define PQ_OFF   8448
#define KS_OFF   25088
#define PK_OFF   33536
#define NORM_OFF 50176
#define SMEM_FLOATS 50432

__global__ __launch_bounds__(256, 1) void hedgehog_main(
    const float* __restrict__ q, const float* __restrict__ k, float* __restrict__ out)
{
    extern __shared__ float sm[];
    float* Qs   = sm + QS_OFF;
    float* Pq   = sm + PQ_OFF;
    float* inv2 = sm + NORM_OFF;          // [128]
    float* rs   = sm + NORM_OFF + 128;    // [128]

    const int tid = threadIdx.x;
    const int tx  = tid & 15;
    const int ty  = tid >> 4;
    const int qt  = blockIdx.x;
    const int bh  = blockIdx.y;
    const int b   = bh >> 4;
    const int h   = bh & 15;
    const int t0  = qt * 128;

    const float* qbase = q + ((size_t)b * 1024 * 16 + h) * 64;   // +t*1024
    const float* kbase = k + ((size_t)b * 1024 * 16 + h) * 64;
    const float* pqb   = g_phiq + (size_t)bh * 1024 * 128;
    const float* pkb   = g_phik + (size_t)bh * 1024 * 128;

    // ---- prologue: async load Qs, Pq, Ks[0], Pk[0] (group 0) ----
    {
        // Qs: 128 rows x 64 floats = 4096 8B-chunks
        #pragma unroll
        for (int p = 0; p < 16; ++p) {
            int idx = p * 256 + tid;
            int r = idx >> 5, c = idx & 31;
            cp8(Qs + r * SA + c * 2, qbase + (size_t)(t0 + r) * 1024 + c * 2);
        }
        // Pq: 128 rows x 128 floats = 8192 chunks
        #pragma unroll
        for (int p = 0; p < 32; ++p) {
            int idx = p * 256 + tid;
            int r = idx >> 6, c = idx & 63;
            cp8(Pq + r * SB + c * 2, pqb + (size_t)(t0 + r) * 128 + c * 2);
        }
        // Ks[0]: 64 x 64 = 2048 chunks
        #pragma unroll
        for (int p = 0; p < 8; ++p) {
            int idx = p * 256 + tid;
            int r = idx >> 5, c = idx & 31;
            cp8(sm + KS_OFF + r * SA + c * 2, kbase + (size_t)r * 1024 + c * 2);
        }
        // Pk[0]: 64 x 128 = 4096 chunks
        #pragma unroll
        for (int p = 0; p < 16; ++p) {
            int idx = p * 256 + tid;
            int r = idx >> 6, c = idx & 63;
            cp8(sm + PK_OFF + r * SB + c * 2, pkb + (size_t)r * 128 + c * 2);
        }
        cp_commit();
    }

    unsigned long long acc[32];
    float rsum1[8];
    #pragma unroll
    for (int i = 0; i < 8; ++i) rsum1[i] = 0.f;

    unsigned int rowb[8];
    #pragma unroll
    for (int i = 0; i < 8; ++i)
        rowb[i] = ((unsigned)(b * 1024 + t0 + ty * 8 + i) * 16 + h) * 1024 + tx;

    const unsigned long long* Aq = reinterpret_cast<const unsigned long long*>(Qs);
    const unsigned long long* Ap = reinterpret_cast<const unsigned long long*>(Pq);

    for (int kt = 0; kt < 16; ++kt) {
        const int cur = kt & 1;
        // issue next tile's loads (buffer was last used at kt-1; trailing barrier
        // of kt-1 protects it)
        if (kt < 15) {
            const int nb = (kt + 1) & 1;
            const int kr = (kt + 1) * 64;
            #pragma unroll
            for (int p = 0; p < 8; ++p) {
                int idx = p * 256 + tid;
                int r = idx >> 5, c = idx & 31;
                cp8(sm + KS_OFF + nb * (64 * SA) + r * SA + c * 2,
                    kbase + (size_t)(kr + r) * 1024 + c * 2);
            }
            #pragma unroll
            for (int p = 0; p < 16; ++p) {
                int idx = p * 256 + tid;
                int r = idx >> 6, c = idx & 63;
                cp8(sm + PK_OFF + nb * (64 * SB) + r * SB + c * 2,
                    pkb + (size_t)(kr + r) * 128 + c * 2);
            }
            cp_commit();
            cp_wait<1>();
        } else {
            cp_wait<0>();
        }
        __syncthreads();

        if (kt == 0) {
            // denominators for map2: inv2[r] = 1 / (Pq[r] . S_k)
            if (tid < 128) {
                const float* skp = g_sk + bh * 128;
                const float* pr  = Pq + tid * SB;
                float s = 0.f;
                #pragma unroll 8
                for (int e = 0; e < 128; ++e) s = fmaf(pr[e], skp[e], s);
                inv2[tid] = 1.0f / s;
            }
            __syncthreads();
        }

        const unsigned long long* Bk =
            reinterpret_cast<const unsigned long long*>(sm + KS_OFF + cur * (64 * SA));
        const unsigned long long* Bp =
            reinterpret_cast<const unsigned long long*>(sm + PK_OFF + cur * (64 * SB));

        // ---- Phase A: scores (inner 64 -> 32 packed pairs) ----
        #pragma unroll
        for (int n = 0; n < 32; ++n) acc[n] = 0ull;
        #pragma unroll 4
        for (int dp = 0; dp < 32; ++dp) {
            unsigned long long av[8], bv[4];
            #pragma unroll
            for (int i = 0; i < 8; ++i) av[i] = Aq[(ty * 8 + i) * 33 + dp];
            #pragma unroll
            for (int j = 0; j < 4; ++j) bv[j] = Bk[(j * 16 + tx) * 33 + dp];
            #pragma unroll
            for (int i = 0; i < 8; ++i)
                #pragma unroll
                for (int j = 0; j < 4; ++j)
                    fma2(acc[i * 4 + j], av[i], bv[j]);
        }
        {
            const unsigned colb = (unsigned)(kt * 64);
            #pragma unroll
            for (int i = 0; i < 8; ++i) {
                #pragma unroll
                for (int j = 0; j < 4; ++j) {
                    float lo, hi; unpack2(acc[i * 4 + j], lo, hi);
                    float p = fexp((lo + hi) * 0.125f);
                    rsum1[i] += p;
                    out[rowb[i] + colb + j * 16] = p;           // unnormalized
                }
            }
        }

        // ---- Phase B: phi_q . phi_k^T (inner 128 -> 64 packed pairs) ----
        #pragma unroll
        for (int n = 0; n < 32; ++n) acc[n] = 0ull;
        #pragma unroll 4
        for (int ep = 0; ep < 64; ++ep) {
            unsigned long long av[8], bv[4];
            #pragma unroll
            for (int i = 0; i < 8; ++i) av[i] = Ap[(ty * 8 + i) * 65 + ep];
            #pragma unroll
            for (int j = 0; j < 4; ++j) bv[j] = Bp[(j * 16 + tx) * 65 + ep];
            #pragma unroll
            for (int i = 0; i < 8; ++i)
                #pragma unroll
                for (int j = 0; j < 4; ++j)
                    fma2(acc[i * 4 + j], av[i], bv[j]);
        }
        {
            const unsigned colb = (unsigned)(kt * 64);
            #pragma unroll
            for (int i = 0; i < 8; ++i) {
                const float s2 = inv2[ty * 8 + i];
                #pragma unroll
                for (int j = 0; j < 4; ++j) {
                    float lo, hi; unpack2(acc[i * 4 + j], lo, hi);
                    out[MAPSZ + rowb[i] + colb + j * 16] = (lo + hi) * s2;  // normalized
                }
            }
        }
        __syncthreads();   // protect buffers before next issue
    }

    // ---- map1 row-sum reduction across the 16 tx lanes ----
    #pragma unroll
    for (int i = 0; i < 8; ++i)
        #pragma unroll
        for (int m = 1; m < 16; m <<= 1)
            rsum1[i] += __shfl_xor_sync(0xffffffffu, rsum1[i], m);
    if (tx == 0) {
        #pragma unroll
        for (int i = 0; i < 8; ++i) rs[ty * 8 + i] = 1.0f / rsum1[i];
    }
    __syncthreads();

    // ---- map1 in-block normalization (L2-hot RMW) ----
    const size_t blockbase = ((size_t)(b * 1024 + t0) * 16 + h) * 1024;
    #pragma unroll 4
    for (int idx = tid; idx < 128 * 256; idx += 256) {
        const int r  = idx >> 8;
        const int c4 = idx & 255;
        const float s = rs[r];
        float4* p = reinterpret_cast<float4*>(out + blockbase + (size_t)r * 16384) + c4;
        float4 v = *p;
        v.x *= s; v.y *= s; v.z *= s; v.w *= s;
        *p = v;
    }
}

// =====================================================================
extern "C" void kernel_launch(void* const* d_in, const int* in_sizes, int n_in,
                              void* d_out, int out_size) {
    const float* q  = (const float*)d_in[0];
    const float* k  = (const float*)d_in[1];
    const float* Wq = (const float*)d_in[2];
    const float* bq = (const float*)d_in[3];
    const float* Wk = (const float*)d_in[4];
    const float* bk = (const float*)d_in[5];
    float* out = (float*)d_out;

    const int smemBytes = SMEM_FLOATS * (int)sizeof(float);
    cudaFuncSetAttribute(hedgehog_main, cudaFuncAttributeMaxDynamicSharedMemorySize, smemBytes);

    hedgehog_prep<<<BB * TT, 256>>>(q, k, Wq, bq, Wk, bk);
    hedgehog_ksum<<<BB * HH, 128>>>();
    hedgehog_main<<<dim3(TT / 128, BB * HH), 256, smemBytes>>>(q, k, out);
}

// round 5
// speedup vs baseline: 1.5588x; 1.1842x over previous
#include <cuda_runtime.h>
#include <cuda_bf16.h>
#include <mma.h>
#include <cstdint>
using namespace nvcuda;

#define MAPSZ 67108864u
typedef unsigned uint;
typedef unsigned long long u64;

// ---------------- device scratch: bf16 hi/lo planes ----------------
__device__ __nv_bfloat16 g_qh[4194304], g_ql[4194304], g_kh[4194304], g_kl[4194304];
__device__ __nv_bfloat16 g_pqh[8388608], g_pql[8388608], g_pkh[8388608], g_pkl[8388608];
__device__ float g_sk[64 * 128];
__device__ float g_inv2[64 * 1024];

// ---------------- helpers ----------------
__device__ __forceinline__ float fexp(float x) {
    float t  = x * 1.4426950408889634f;
    float fi = t + 12582912.0f;
    int   n  = __float_as_int(fi) - 0x4B400000;
    float f  = t - (fi - 12582912.0f);
    float p  = 1.54035304e-4f;
    p = fmaf(p, f, 1.33335581e-3f);
    p = fmaf(p, f, 9.61812911e-3f);
    p = fmaf(p, f, 5.55041087e-2f);
    p = fmaf(p, f, 2.40226507e-1f);
    p = fmaf(p, f, 6.93147181e-1f);
    p = fmaf(p, f, 1.0f);
    return __int_as_float(__float_as_int(p) + (n << 23));
}
__device__ __forceinline__ float frcp(float x) { float r; asm("rcp.approx.ftz.f32 %0,%1;" : "=f"(r) : "f"(x)); return r; }
__device__ __forceinline__ void fma2(u64& a, u64 x, u64 w) { asm volatile("fma.rn.f32x2 %0,%1,%2,%0;" : "+l"(a) : "l"(x), "l"(w)); }
__device__ __forceinline__ uint packbf(float hi, float lo) { uint r; asm("cvt.rn.bf16x2.f32 %0,%1,%2;" : "=r"(r) : "f"(hi), "f"(lo)); return r; }
__device__ __forceinline__ float lowf(uint w)  { return __int_as_float(w << 16); }
__device__ __forceinline__ float highf(uint w) { return __int_as_float(w & 0xFFFF0000u); }
__device__ __forceinline__ uint smem_u32(const void* p) {
    uint a; asm("{ .reg .u64 t; cvta.to.shared.u64 t,%1; cvt.u32.u64 %0,t; }" : "=r"(a) : "l"(p)); return a;
}
__device__ __forceinline__ void cp16(uint dst, const void* src) {
    asm volatile("cp.async.cg.shared.global [%0],[%1],16;" :: "r"(dst), "l"(src));
}
#define CP_COMMIT() asm volatile("cp.async.commit_group;")
#define CP_WAIT0()  asm volatile("cp.async.wait_group 0;")
#define CP_WAIT1()  asm volatile("cp.async.wait_group 1;")

// =====================================================================
// Kernel 1: feature maps -> bf16 hi/lo planes for q,k,phiq,phik
// grid 512 = tensor(2) x b(4) x h(16) x tchunk(4x256); 256 threads
// =====================================================================
__global__ __launch_bounds__(256) void hedgehog_prep2(
    const float* __restrict__ q, const float* __restrict__ k,
    const float* __restrict__ Wq, const float* __restrict__ bq,
    const float* __restrict__ Wk, const float* __restrict__ bk)
{
    __shared__ u64 Wp[64 * 32];
    __shared__ u64 bp[32];
    const int tid = threadIdx.x, bid = blockIdx.x;
    const int tensor = bid >> 8, rem = bid & 255;
    const int b = rem >> 6, h = (rem >> 2) & 15, t0 = (rem & 3) * 256;
    const float* W  = tensor ? Wk : Wq;
    const float* bi = tensor ? bk : bq;
    const float* x  = tensor ? k  : q;

    float* Wpf = (float*)Wp;
    #pragma unroll
    for (int i = 0; i < 16; ++i) {
        int idx = i * 256 + tid;
        int e = idx >> 6, d = idx & 63;
        Wpf[(d * 32 + (e >> 1)) * 2 + (e & 1)] = W[idx];
    }
    if (tid < 64) ((float*)bp)[tid] = bi[tid];
    __syncthreads();

    const size_t xi = ((size_t)(b * 1024 + t0 + tid) * 16 + h) * 64;
    const float4* xp = (const float4*)(x + xi);
    uint* xhw = (uint*)((tensor ? g_kh : g_qh) + xi);
    uint* xlw = (uint*)((tensor ? g_kl : g_ql) + xi);

    u64 yp[32];
    #pragma unroll
    for (int ep = 0; ep < 32; ++ep) yp[ep] = bp[ep];

    #pragma unroll
    for (int d4 = 0; d4 < 16; ++d4) {
        float4 xv = xp[d4];
        uint h0 = packbf(xv.y, xv.x), h1 = packbf(xv.w, xv.z);
        xhw[d4 * 2] = h0; xhw[d4 * 2 + 1] = h1;
        xlw[d4 * 2]     = packbf(xv.y - highf(h0), xv.x - lowf(h0));
        xlw[d4 * 2 + 1] = packbf(xv.w - highf(h1), xv.z - lowf(h1));
        float xs4[4] = {xv.x, xv.y, xv.z, xv.w};
        #pragma unroll
        for (int u = 0; u < 4; ++u) {
            u64 xx; asm("mov.b64 %0,{%1,%1};" : "=l"(xx) : "f"(xs4[u]));
            const u64* wr = Wp + (d4 * 4 + u) * 32;
            #pragma unroll
            for (int ep = 0; ep < 32; ++ep) fma2(yp[ep], xx, wr[ep]);
        }
    }

    float ev[64];
    #pragma unroll
    for (int ep = 0; ep < 32; ++ep) {
        float y0, y1; asm("mov.b64 {%0,%1},%2;" : "=f"(y0), "=f"(y1) : "l"(yp[ep]));
        ev[2 * ep] = fexp(y0); ev[2 * ep + 1] = fexp(y1);
    }
    const size_t pi = (((size_t)(b * 16 + h)) * 1024 + t0 + tid) * 128;
    uint* ph = (uint*)((tensor ? g_pkh : g_pqh) + pi);
    uint* pl = (uint*)((tensor ? g_pkl : g_pql) + pi);
    #pragma unroll
    for (int p = 0; p < 64; ++p) {
        float v0 = (p < 32) ? ev[2 * p]     : frcp(ev[2 * p - 64]);
        float v1 = (p < 32) ? ev[2 * p + 1] : frcp(ev[2 * p - 63]);
        uint hw = packbf(v1, v0);
        ph[p] = hw;
        pl[p] = packbf(v1 - highf(hw), v0 - lowf(hw));
    }
}

// =====================================================================
// Kernel 1b: S_k ; Kernel 1c: inv2 = 1/(phiq . S_k)
// =====================================================================
__global__ __launch_bounds__(256) void hedgehog_ksum() {
    __shared__ float part[256];
    const int bh = blockIdx.x, tid = threadIdx.x;
    const int e = tid & 127, hp = tid >> 7;
    const __nv_bfloat16* H = g_pkh + (size_t)bh * 131072 + (size_t)hp * 512 * 128 + e;
    const __nv_bfloat16* L = g_pkl + (size_t)bh * 131072 + (size_t)hp * 512 * 128 + e;
    float s = 0.f;
    #pragma unroll 4
    for (int t = 0; t < 512; ++t) s += __bfloat162float(H[(size_t)t * 128]) + __bfloat162float(L[(size_t)t * 128]);
    part[tid] = s;
    __syncthreads();
    if (tid < 128) g_sk[bh * 128 + tid] = part[tid] + part[tid + 128];
}
__global__ __launch_bounds__(256) void hedgehog_inv2() {
    __shared__ float sk[128];
    const int bid = blockIdx.x, tid = threadIdx.x;
    const int bh = bid >> 2, t = (bid & 3) * 256 + tid;
    if (tid < 128) sk[tid] = g_sk[bh * 128 + tid];
    __syncthreads();
    const uint* H = (const uint*)(g_pqh + ((size_t)bh * 1024 + t) * 128);
    const uint* L = (const uint*)(g_pql + ((size_t)bh * 1024 + t) * 128);
    float s = 0.f;
    #pragma unroll 8
    for (int p = 0; p < 64; ++p) {
        uint hw = H[p], lw = L[p];
        s = fmaf(lowf(hw) + lowf(lw), sk[2 * p], s);
        s = fmaf(highf(hw) + highf(lw), sk[2 * p + 1], s);
    }
    g_inv2[bh * 1024 + t] = 1.0f / s;
}

// =====================================================================
// Kernel 2: wmma bf16 hi/lo main. grid (8,64), 256 threads (8 warps, 4x2).
// SMEM: Qh/Ql [128][72]b, Pq'h/Pq'l [128][136]b (inv2-scaled),
//       2 x (Kh/Kl [64][72]b + Pkh/Pkl [64][136]b), rs[128]f
// =====================================================================
#define QH_OFF   0u
#define QL_OFF   18432u
#define PQH_OFF  36864u
#define PQL_OFF  71680u
#define B0_OFF   106496u
#define BUFSZ    53248u
#define RS_OFF   212992u
#define SMEM_BYTES 213504

__device__ __forceinline__ void stage_B(uint sbuf, int b, int h, int bh, int kr, int tid) {
    #pragma unroll
    for (int i = 0; i < 4; ++i) {            // k planes: 1024 chunks
        int idx = i * 256 + tid;
        int pl = idx >> 9, r = (idx >> 3) & 63, c = idx & 7;
        const __nv_bfloat16* s = (pl ? g_kl : g_kh) + ((size_t)((b * 1024 + kr + r) * 16 + h)) * 64 + c * 8;
        cp16(sbuf + (uint)pl * 9216u + r * 144u + c * 16u, s);
    }
    #pragma unroll
    for (int i = 0; i < 8; ++i) {            // phi planes: 2048 chunks
        int idx = i * 256 + tid;
        int pl = idx >> 10, r = (idx >> 4) & 63, c = idx & 15;
        const __nv_bfloat16* s = (pl ? g_pkl : g_pkh) + ((size_t)bh * 1024 + kr + r) * 128 + c * 8;
        cp16(sbuf + 18432u + (uint)pl * 17408u + r * 272u + c * 16u, s);
    }
}

__global__ __launch_bounds__(256, 1) void hedgehog_main(float* __restrict__ out)
{
    extern __shared__ __align__(16) char sm[];
    const uint sb = smem_u32(sm);
    const int tid = threadIdx.x, w = tid >> 5;
    const int wr = w >> 1, wc = w & 1;
    const int qt = blockIdx.x, bh = blockIdx.y;
    const int b = bh >> 4, h = bh & 15, t0 = qt * 128;

    // ---- prologue: async q planes + B buf0 ----
    #pragma unroll
    for (int i = 0; i < 8; ++i) {
        int idx = i * 256 + tid;
        int pl = idx >> 10, r = (idx >> 3) & 127, c = idx & 7;
        const __nv_bfloat16* s = (pl ? g_ql : g_qh) + ((size_t)((b * 1024 + t0 + r) * 16 + h)) * 64 + c * 8;
        cp16(sb + (pl ? QL_OFF : QH_OFF) + r * 144u + c * 16u, s);
    }
    stage_B(sb + B0_OFF, b, h, bh, 0, tid);
    CP_COMMIT();

    // ---- phi_q scaled by inv2, re-split hi/lo (regular ld/st) ----
    {
        const int r = tid >> 1, hf = tid & 1;
        const float s2 = g_inv2[bh * 1024 + t0 + r];
        const uint* H = (const uint*)(g_pqh + ((size_t)bh * 1024 + t0 + r) * 128) + hf * 32;
        const uint* L = (const uint*)(g_pql + ((size_t)bh * 1024 + t0 + r) * 128) + hf * 32;
        uint* dh = (uint*)(sm + PQH_OFF + r * 272 + hf * 128);
        uint* dl = (uint*)(sm + PQL_OFF + r * 272 + hf * 128);
        #pragma unroll
        for (int i = 0; i < 32; ++i) {
            uint hw = H[i], lw = L[i];
            float f0 = (lowf(hw) + lowf(lw)) * s2;
            float f1 = (highf(hw) + highf(lw)) * s2;
            uint nh = packbf(f1, f0);
            dh[i] = nh;
            dl[i] = packbf(f1 - highf(nh), f0 - lowf(nh));
        }
    }
    __syncthreads();

    const __nv_bfloat16* Qh = (const __nv_bfloat16*)(sm + QH_OFF);
    const __nv_bfloat16* Ql = (const __nv_bfloat16*)(sm + QL_OFF);
    const __nv_bfloat16* Ph = (const __nv_bfloat16*)(sm + PQH_OFF);
    const __nv_bfloat16* Pl = (const __nv_bfloat16*)(sm + PQL_OFF);
    float* out1 = out + ((size_t)((b * 1024 + t0) * 16 + h)) * 1024;
    float* out2 = out1 + MAPSZ;

    for (int kt = 0; kt < 16; ++kt) {
        if (kt < 15) { stage_B(sb + B0_OFF + ((kt + 1) & 1) * BUFSZ, b, h, bh, (kt + 1) * 64, tid); CP_COMMIT(); CP_WAIT1(); }
        else CP_WAIT0();
        __syncthreads();
        const __nv_bfloat16* Kh = (const __nv_bfloat16*)(sm + B0_OFF + (kt & 1) * BUFSZ);
        const __nv_bfloat16* Kl = (const __nv_bfloat16*)((const char*)Kh + 9216);
        const __nv_bfloat16* Fh = (const __nv_bfloat16*)((const char*)Kh + 18432);
        const __nv_bfloat16* Fl = (const __nv_bfloat16*)((const char*)Kh + 18432 + 17408);

        wmma::fragment<wmma::accumulator, 16, 16, 16, float> acc[2][2];

        // ---- phase A: scores = q.k^T (K=64) ----
        #pragma unroll
        for (int i = 0; i < 2; ++i)
            #pragma unroll
            for (int j = 0; j < 2; ++j) wmma::fill_fragment(acc[i][j], 0.0f);
        #pragma unroll
        for (int ks = 0; ks < 4; ++ks) {
            wmma::fragment<wmma::matrix_a, 16, 16, 16, __nv_bfloat16, wmma::row_major> ah[2], al[2];
            wmma::fragment<wmma::matrix_b, 16, 16, 16, __nv_bfloat16, wmma::col_major> bhf[2], blf[2];
            #pragma unroll
            for (int i = 0; i < 2; ++i) {
                wmma::load_matrix_sync(ah[i], Qh + (wr * 32 + i * 16) * 72 + ks * 16, 72);
                wmma::load_matrix_sync(al[i], Ql + (wr * 32 + i * 16) * 72 + ks * 16, 72);
            }
            #pragma unroll
            for (int j = 0; j < 2; ++j) {
                wmma::load_matrix_sync(bhf[j], Kh + (wc * 32 + j * 16) * 72 + ks * 16, 72);
                wmma::load_matrix_sync(blf[j], Kl + (wc * 32 + j * 16) * 72 + ks * 16, 72);
            }
            #pragma unroll
            for (int i = 0; i < 2; ++i)
                #pragma unroll
                for (int j = 0; j < 2; ++j) {
                    wmma::mma_sync(acc[i][j], ah[i], bhf[j], acc[i][j]);
                    wmma::mma_sync(acc[i][j], al[i], bhf[j], acc[i][j]);
                    wmma::mma_sync(acc[i][j], ah[i], blf[j], acc[i][j]);
                }
        }
        #pragma unroll
        for (int i = 0; i < 2; ++i)
            #pragma unroll
            for (int j = 0; j < 2; ++j) {
                #pragma unroll
                for (int e = 0; e < acc[i][j].num_elements; ++e)
                    acc[i][j].x[e] = fexp(acc[i][j].x[e] * 0.125f);
                wmma::store_matrix_sync(out1 + (size_t)(wr * 32 + i * 16) * 16384
                                        + kt * 64 + wc * 32 + j * 16,
                                        acc[i][j], 16384, wmma::mem_row_major);
            }

        // ---- phase B: (inv2*phi_q).phi_k^T (K=128), already normalized ----
        #pragma unroll
        for (int i = 0; i < 2; ++i)
            #pragma unroll
            for (int j = 0; j < 2; ++j) wmma::fill_fragment(acc[i][j], 0.0f);
        #pragma unroll
        for (int ks = 0; ks < 8; ++ks) {
            wmma::fragment<wmma::matrix_a, 16, 16, 16, __nv_bfloat16, wmma::row_major> ah[2], al[2];
            wmma::fragment<wmma::matrix_b, 16, 16, 16, __nv_bfloat16, wmma::col_major> bhf[2], blf[2];
            #pragma unroll
            for (int i = 0; i < 2; ++i) {
                wmma::load_matrix_sync(ah[i], Ph + (wr * 32 + i * 16) * 136 + ks * 16, 136);
                wmma::load_matrix_sync(al[i], Pl + (wr * 32 + i * 16) * 136 + ks * 16, 136);
            }
            #pragma unroll
            for (int j = 0; j < 2; ++j) {
                wmma::load_matrix_sync(bhf[j], Fh + (wc * 32 + j * 16) * 136 + ks * 16, 136);
                wmma::load_matrix_sync(blf[j], Fl + (wc * 32 + j * 16) * 136 + ks * 16, 136);
            }
            #pragma unroll
            for (int i = 0; i < 2; ++i)
                #pragma unroll
                for (int j = 0; j < 2; ++j) {
                    wmma::mma_sync(acc[i][j], ah[i], bhf[j], acc[i][j]);
                    wmma::mma_sync(acc[i][j], al[i], bhf[j], acc[i][j]);
                    wmma::mma_sync(acc[i][j], ah[i], blf[j], acc[i][j]);
                }
        }
        #pragma unroll
        for (int i = 0; i < 2; ++i)
            #pragma unroll
            for (int j = 0; j < 2; ++j)
                wmma::store_matrix_sync(out2 + (size_t)(wr * 32 + i * 16) * 16384
                                        + kt * 64 + wc * 32 + j * 16,
                                        acc[i][j], 16384, wmma::mem_row_major);
        __syncthreads();
    }

    // ---- map1 row sums (L2-hot) ----
    float* rs = (float*)(sm + RS_OFF);
    {
        const int r = tid >> 1, hf = tid & 1;
        const float4* p = (const float4*)(out1 + (size_t)r * 16384 + hf * 512);
        float s = 0.f;
        #pragma unroll 8
        for (int i = 0; i < 128; ++i) { float4 v = p[i]; s += (v.x + v.y) + (v.z + v.w); }
        s += __shfl_xor_sync(0xffffffffu, s, 1);
        rs[r] = 1.0f / s;
    }
    __syncthreads();

    // ---- map1 RMW normalize (L2-hot) ----
    #pragma unroll 4
    for (int idx = tid; idx < 32768; idx += 256) {
        const int r = idx >> 8, c4 = idx & 255;
        const float s = rs[r];
        float4* p = (float4*)(out1 + (size_t)r * 16384) + c4;
        float4 u = *p;
        u.x *= s; u.y *= s; u.z *= s; u.w *= s;
        *p = u;
    }
}

// =====================================================================
extern "C" void kernel_launch(void* const* d_in, const int* in_sizes, int n_in,
                              void* d_out, int out_size) {
    const float* q  = (const float*)d_in[0];
    const float* k  = (const float*)d_in[1];
    const float* Wq = (const float*)d_in[2];
    const float* bq = (const float*)d_in[3];
    const float* Wk = (const float*)d_in[4];
    const float* bk = (const float*)d_in[5];
    float* out = (float*)d_out;

    cudaFuncSetAttribute(hedgehog_main, cudaFuncAttributeMaxDynamicSharedMemorySize, SMEM_BYTES);
    hedgehog_prep2<<<512, 256>>>(q, k, Wq, bq, Wk, bk);
    hedgehog_ksum<<<64, 256>>>();
    hedgehog_inv2<<<256, 256>>>();
    hedgehog_main<<<dim3(8, 64), 256, SMEM_BYTES>>>(out);
}

// round 6
// speedup vs baseline: 4.0956x; 2.6275x over previous
#include <cuda_runtime.h>
#include <cuda_fp16.h>
#include <cstdint>

#define MAPSZ 67108864u
typedef unsigned uint;
typedef unsigned long long u64;

// ---------------- device scratch: single fp16 planes ----------------
__device__ __half g_q16[4194304];     // q * 0.125, [b][t][h][d]
__device__ __half g_k16[4194304];     // k,        [b][t][h][d]
__device__ __half g_pq16[8388608];    // phi_q,    [bh][t][128]
__device__ __half g_pk16[8388608];    // phi_k,    [bh][t][128]
__device__ float  g_skp[64 * 8 * 128];  // partial sums of phi_k

// ---------------- helpers ----------------
__device__ __forceinline__ float fexp(float x) {
    float t  = x * 1.4426950408889634f;
    float fi = t + 12582912.0f;
    int   n  = __float_as_int(fi) - 0x4B400000;
    float f  = t - (fi - 12582912.0f);
    float p  = 1.54035304e-4f;
    p = fmaf(p, f, 1.33335581e-3f);
    p = fmaf(p, f, 9.61812911e-3f);
    p = fmaf(p, f, 5.55041087e-2f);
    p = fmaf(p, f, 2.40226507e-1f);
    p = fmaf(p, f, 6.93147181e-1f);
    p = fmaf(p, f, 1.0f);
    return __int_as_float(__float_as_int(p) + (n << 23));
}
__device__ __forceinline__ float frcp(float x) { float r; asm("rcp.approx.ftz.f32 %0,%1;" : "=f"(r) : "f"(x)); return r; }
__device__ __forceinline__ void fma2(u64& a, u64 x, u64 w) { asm volatile("fma.rn.f32x2 %0,%1,%2,%0;" : "+l"(a) : "l"(x), "l"(w)); }
__device__ __forceinline__ uint packh(float hi, float lo) { uint r; asm("cvt.rn.f16x2.f32 %0,%1,%2;" : "=r"(r) : "f"(hi), "f"(lo)); return r; }
__device__ __forceinline__ uint smem_u32(const void* p) {
    uint a; asm("{ .reg .u64 t; cvta.to.shared.u64 t,%1; cvt.u32.u64 %0,t; }" : "=r"(a) : "l"(p)); return a;
}
__device__ __forceinline__ void cp16(uint dst, const void* src) {
    asm volatile("cp.async.cg.shared.global [%0],[%1],16;" :: "r"(dst), "l"(src));
}
#define CP_COMMIT() asm volatile("cp.async.commit_group;")
#define CP_WAIT0()  asm volatile("cp.async.wait_group 0;")
#define CP_WAIT1()  asm volatile("cp.async.wait_group 1;")

__device__ __forceinline__ void ldsm4(uint* r, uint addr) {
    asm volatile("ldmatrix.sync.aligned.m8n8.x4.shared.b16 {%0,%1,%2,%3},[%4];"
                 : "=r"(r[0]), "=r"(r[1]), "=r"(r[2]), "=r"(r[3]) : "r"(addr));
}
__device__ __forceinline__ void mma168(float* c, const uint* a, uint b0, uint b1) {
    asm volatile("mma.sync.aligned.m16n8k16.row.col.f32.f16.f16.f32 "
                 "{%0,%1,%2,%3},{%4,%5,%6,%7},{%8,%9},{%0,%1,%2,%3};"
                 : "+f"(c[0]), "+f"(c[1]), "+f"(c[2]), "+f"(c[3])
                 : "r"(a[0]), "r"(a[1]), "r"(a[2]), "r"(a[3]), "r"(b0), "r"(b1));
}
__device__ __forceinline__ void st2(float* p, float a, float b) {
    asm volatile("st.global.v2.f32 [%0],{%1,%2};" :: "l"(p), "f"(a), "f"(b) : "memory");
}

// =====================================================================
// Kernel 1: feature maps -> fp16 planes. grid 512 = tensor*b*h*tchunk.
// =====================================================================
__global__ __launch_bounds__(256) void hedgehog_prep2(
    const float* __restrict__ q, const float* __restrict__ k,
    const float* __restrict__ Wq, const float* __restrict__ bq,
    const float* __restrict__ Wk, const float* __restrict__ bk)
{
    __shared__ u64 Wp[64 * 32];
    __shared__ u64 bp[32];
    const int tid = threadIdx.x, bid = blockIdx.x;
    const int tensor = bid >> 8, rem = bid & 255;
    const int b = rem >> 6, h = (rem >> 2) & 15, t0 = (rem & 3) * 256;
    const float* W  = tensor ? Wk : Wq;
    const float* bi = tensor ? bk : bq;
    const float* x  = tensor ? k  : q;
    const float sc  = tensor ? 1.0f : 0.125f;

    float* Wpf = (float*)Wp;
    #pragma unroll
    for (int i = 0; i < 16; ++i) {
        int idx = i * 256 + tid;
        int e = idx >> 6, d = idx & 63;
        Wpf[(d * 32 + (e >> 1)) * 2 + (e & 1)] = W[idx];
    }
    if (tid < 64) ((float*)bp)[tid] = bi[tid];
    __syncthreads();

    const size_t xi = ((size_t)(b * 1024 + t0 + tid) * 16 + h) * 64;
    const float4* xp = (const float4*)(x + xi);
    uint* xw = (uint*)((tensor ? g_k16 : g_q16) + xi);

    u64 yp[32];
    #pragma unroll
    for (int ep = 0; ep < 32; ++ep) yp[ep] = bp[ep];

    #pragma unroll
    for (int d4 = 0; d4 < 16; ++d4) {
        float4 xv = xp[d4];
        xw[d4 * 2]     = packh(xv.y * sc, xv.x * sc);
        xw[d4 * 2 + 1] = packh(xv.w * sc, xv.z * sc);
        float xs4[4] = {xv.x, xv.y, xv.z, xv.w};
        #pragma unroll
        for (int u = 0; u < 4; ++u) {
            u64 xx; asm("mov.b64 %0,{%1,%1};" : "=l"(xx) : "f"(xs4[u]));
            const u64* wr = Wp + (d4 * 4 + u) * 32;
            #pragma unroll
            for (int ep = 0; ep < 32; ++ep) fma2(yp[ep], xx, wr[ep]);
        }
    }

    float ev[64];
    #pragma unroll
    for (int ep = 0; ep < 32; ++ep) {
        float y0, y1; asm("mov.b64 {%0,%1},%2;" : "=f"(y0), "=f"(y1) : "l"(yp[ep]));
        ev[2 * ep] = fexp(y0); ev[2 * ep + 1] = fexp(y1);
    }
    uint* pw = (uint*)((tensor ? g_pk16 : g_pq16) + (((size_t)(b * 16 + h)) * 1024 + t0 + tid) * 128);
    #pragma unroll
    for (int p = 0; p < 32; ++p) pw[p] = packh(ev[2 * p + 1], ev[2 * p]);
    #pragma unroll
    for (int p = 0; p < 32; ++p) pw[32 + p] = packh(frcp(ev[2 * p + 1]), frcp(ev[2 * p]));
}

// =====================================================================
// Kernel 1b: partial column-sums of phi_k. grid 512 = bh(64) x chunk(8).
// =====================================================================
__global__ __launch_bounds__(128) void hedgehog_ksum() {
    const int blk = blockIdx.x, bh = blk >> 3, ch = blk & 7;
    const int e = threadIdx.x;
    const __half* src = g_pk16 + ((size_t)bh * 1024 + ch * 128) * 128 + e;
    float s = 0.f;
    #pragma unroll 4
    for (int t = 0; t < 128; ++t) s += __half2float(src[(size_t)t * 128]);
    g_skp[blk * 128 + e] = s;
}

// =====================================================================
// Kernel 2: fp16 mma.sync main. grid (8,64), 512 threads (16 warps 4x4).
// SMEM: Q[128x72h] | PQ[128x136h] | 2 x (K[128x72h] + PK[128x136h]) | sk | inv2 | rs
// Sweep1: map1 rowsums (no store) + map2 store (normalized via inv2).
// Sweep2: map1 recompute + store normalized. No RMW, no sum pass.
// =====================================================================
#define QOFF  0u
#define PQOFF 18432u
#define B0OFF 53248u
#define BSZ   53248u
#define SKOFF 159744u
#define IVOFF 160256u
#define RSOFF 160768u
#define SMEMB 161280

template<bool WITH_PK>
__device__ __forceinline__ void stageB(uint sb, uint bufo, int b, int h, int bh, int kr, int tid) {
    #pragma unroll
    for (int i = 0; i < 2; ++i) {                   // K tile: 128 rows x 64h
        int idx = i * 512 + tid;
        int r = idx >> 3, c = idx & 7;
        cp16(sb + bufo + r * 144u + c * 16u,
             g_k16 + ((size_t)((b * 1024 + kr + r) * 16 + h)) * 64 + c * 8);
    }
    if (WITH_PK) {
        #pragma unroll
        for (int i = 0; i < 4; ++i) {               // PK tile: 128 rows x 128h
            int idx = i * 512 + tid;
            int r = idx >> 4, c = idx & 15;
            cp16(sb + bufo + 18432u + r * 272u + c * 16u,
                 g_pk16 + ((size_t)bh * 1024 + kr + r) * 128 + c * 8);
        }
    }
}

__global__ __launch_bounds__(512, 1) void hedgehog_main(float* __restrict__ out)
{
    extern __shared__ __align__(16) char sm[];
    const uint sb = smem_u32(sm);
    const int tid = threadIdx.x, w = tid >> 5, l = tid & 31;
    const int wr = w >> 2, wc = w & 3;
    const int qt = blockIdx.x, bh = blockIdx.y;
    const int b = bh >> 4, h = bh & 15, t0 = qt * 128;
    float* skf = (float*)(sm + SKOFF);
    float* ivf = (float*)(sm + IVOFF);
    float* rsf = (float*)(sm + RSOFF);

    // ---- prologue: stage Q, PQ, buf0 (group 0) ----
    #pragma unroll
    for (int i = 0; i < 2; ++i) {
        int idx = i * 512 + tid;
        int r = idx >> 3, c = idx & 7;
        cp16(sb + QOFF + r * 144u + c * 16u,
             g_q16 + ((size_t)((b * 1024 + t0 + r) * 16 + h)) * 64 + c * 8);
    }
    #pragma unroll
    for (int i = 0; i < 4; ++i) {
        int idx = i * 512 + tid;
        int r = idx >> 4, c = idx & 15;
        cp16(sb + PQOFF + r * 272u + c * 16u,
             g_pq16 + ((size_t)bh * 1024 + t0 + r) * 128 + c * 8);
    }
    stageB<true>(sb, B0OFF, b, h, bh, 0, tid);
    CP_COMMIT();

    if (tid < 128) {                                 // S_k from partials
        float s = 0.f;
        #pragma unroll
        for (int c = 0; c < 8; ++c) s += g_skp[(bh * 8 + c) * 128 + tid];
        skf[tid] = s;
        rsf[tid] = 0.f;
    }
    CP_WAIT0();
    __syncthreads();

    if (tid < 128) {                                 // inv2[r] = 1/(phi_q[r].S_k)
        const uint* pr = (const uint*)(sm + PQOFF + tid * 272);
        float s = 0.f;
        #pragma unroll 16
        for (int i = 0; i < 64; ++i) {
            float2 v = __half22float2(*(const __half2*)(pr + i));
            s = fmaf(v.x, skf[2 * i], s);
            s = fmaf(v.y, skf[2 * i + 1], s);
        }
        ivf[tid] = 1.0f / s;
    }
    __syncthreads();

    // ---- per-thread ldmatrix/store addressing ----
    const uint aK = (uint)(l >> 4) * 16;
    const uint qA = sb + QOFF  + (wr * 32 + (l & 15)) * 144u + aK;
    const uint pA = sb + PQOFF + (wr * 32 + (l & 15)) * 272u + aK;
    const uint bRow = (uint)((l & 7) + ((l >> 3) & 1) * 8);
    const uint kBrel = (wc * 32 + bRow) * 144u + aK;
    const uint pBrel = (wc * 32 + bRow) * 272u + aK + 18432u;

    float* o1 = out + ((size_t)((b * 1024 + t0 + wr * 32 + (l >> 2)) * 16 + h)) * 1024
                + wc * 32 + 2 * (l & 3);
    float* o2 = o1 + MAPSZ;

    float iv0[2], iv1[2];
    #pragma unroll
    for (int mi = 0; mi < 2; ++mi) {
        iv0[mi] = ivf[wr * 32 + mi * 16 + (l >> 2)];
        iv1[mi] = ivf[wr * 32 + mi * 16 + (l >> 2) + 8];
    }
    float rlo[2] = {0.f, 0.f}, rhi[2] = {0.f, 0.f};

    // ================= sweep 1 =================
    for (int kt = 0; kt < 8; ++kt) {
        if (kt < 7) { stageB<true>(sb, B0OFF + ((kt + 1) & 1) * BSZ, b, h, bh, (kt + 1) * 128, tid); CP_COMMIT(); CP_WAIT1(); }
        else CP_WAIT0();
        __syncthreads();
        const uint bufo = B0OFF + (kt & 1) * BSZ;

        // ---- map1: scores (K=64) ----
        float acc[2][4][4];
        #pragma unroll
        for (int mi = 0; mi < 2; ++mi)
            #pragma unroll
            for (int nj = 0; nj < 4; ++nj)
                #pragma unroll
                for (int e = 0; e < 4; ++e) acc[mi][nj][e] = 0.f;
        #pragma unroll
        for (int ks = 0; ks < 4; ++ks) {
            uint A0[4], A1[4], B0[4], B1[4];
            ldsm4(A0, qA + ks * 32);
            ldsm4(A1, qA + 2304 + ks * 32);
            ldsm4(B0, sb + bufo + kBrel + ks * 32);
            ldsm4(B1, sb + bufo + kBrel + 2304 + ks * 32);
            mma168(acc[0][0], A0, B0[0], B0[2]); mma168(acc[0][1], A0, B0[1], B0[3]);
            mma168(acc[0][2], A0, B1[0], B1[2]); mma168(acc[0][3], A0, B1[1], B1[3]);
            mma168(acc[1][0], A1, B0[0], B0[2]); mma168(acc[1][1], A1, B0[1], B0[3]);
            mma168(acc[1][2], A1, B1[0], B1[2]); mma168(acc[1][3], A1, B1[1], B1[3]);
        }
        #pragma unroll
        for (int mi = 0; mi < 2; ++mi)
            #pragma unroll
            for (int nj = 0; nj < 4; ++nj) {
                rlo[mi] += __expf(acc[mi][nj][0]) + __expf(acc[mi][nj][1]);
                rhi[mi] += __expf(acc[mi][nj][2]) + __expf(acc[mi][nj][3]);
            }

        // ---- map2: phi (K=128), normalized, stored ----
        #pragma unroll
        for (int mi = 0; mi < 2; ++mi)
            #pragma unroll
            for (int nj = 0; nj < 4; ++nj)
                #pragma unroll
                for (int e = 0; e < 4; ++e) acc[mi][nj][e] = 0.f;
        #pragma unroll
        for (int ks = 0; ks < 8; ++ks) {
            uint A0[4], A1[4], B0[4], B1[4];
            ldsm4(A0, pA + ks * 32);
            ldsm4(A1, pA + 4352 + ks * 32);
            ldsm4(B0, sb + bufo + pBrel + ks * 32);
            ldsm4(B1, sb + bufo + pBrel + 4352 + ks * 32);
            mma168(acc[0][0], A0, B0[0], B0[2]); mma168(acc[0][1], A0, B0[1], B0[3]);
            mma168(acc[0][2], A0, B1[0], B1[2]); mma168(acc[0][3], A0, B1[1], B1[3]);
            mma168(acc[1][0], A1, B0[0], B0[2]); mma168(acc[1][1], A1, B0[1], B0[3]);
            mma168(acc[1][2], A1, B1[0], B1[2]); mma168(acc[1][3], A1, B1[1], B1[3]);
        }
        #pragma unroll
        for (int mi = 0; mi < 2; ++mi)
            #pragma unroll
            for (int nj = 0; nj < 4; ++nj) {
                float* p = o2 + (size_t)mi * 262144 + kt * 128 + nj * 8;
                st2(p,                 acc[mi][nj][0] * iv0[mi], acc[mi][nj][1] * iv0[mi]);
                st2(p + 8 * 16384,     acc[mi][nj][2] * iv1[mi], acc[mi][nj][3] * iv1[mi]);
            }
        __syncthreads();
    }

    // ---- rowsum reduce -> rs ----
    #pragma unroll
    for (int mi = 0; mi < 2; ++mi) {
        rlo[mi] += __shfl_xor_sync(0xffffffffu, rlo[mi], 1);
        rlo[mi] += __shfl_xor_sync(0xffffffffu, rlo[mi], 2);
        rhi[mi] += __shfl_xor_sync(0xffffffffu, rhi[mi], 1);
        rhi[mi] += __shfl_xor_sync(0xffffffffu, rhi[mi], 2);
        if ((l & 3) == 0) {
            atomicAdd(&rsf[wr * 32 + mi * 16 + (l >> 2)], rlo[mi]);
            atomicAdd(&rsf[wr * 32 + mi * 16 + (l >> 2) + 8], rhi[mi]);
        }
    }
    __syncthreads();
    if (tid < 128) rsf[tid] = 1.0f / rsf[tid];
    __syncthreads();

    float rv0[2], rv1[2];
    #pragma unroll
    for (int mi = 0; mi < 2; ++mi) {
        rv0[mi] = rsf[wr * 32 + mi * 16 + (l >> 2)];
        rv1[mi] = rsf[wr * 32 + mi * 16 + (l >> 2) + 8];
    }

    // ================= sweep 2: map1 recompute + store =================
    stageB<false>(sb, B0OFF, b, h, bh, 0, tid);
    CP_COMMIT();
    for (int kt = 0; kt < 8; ++kt) {
        if (kt < 7) { stageB<false>(sb, B0OFF + ((kt + 1) & 1) * BSZ, b, h, bh, (kt + 1) * 128, tid); CP_COMMIT(); CP_WAIT1(); }
        else CP_WAIT0();
        __syncthreads();
        const uint bufo = B0OFF + (kt & 1) * BSZ;

        float acc[2][4][4];
        #pragma unroll
        for (int mi = 0; mi < 2; ++mi)
            #pragma unroll
            for (int nj = 0; nj < 4; ++nj)
                #pragma unroll
                for (int e = 0; e < 4; ++e) acc[mi][nj][e] = 0.f;
        #pragma unroll
        for (int ks = 0; ks < 4; ++ks) {
            uint A0[4], A1[4], B0[4], B1[4];
            ldsm4(A0, qA + ks * 32);
            ldsm4(A1, qA + 2304 + ks * 32);
            ldsm4(B0, sb + bufo + kBrel + ks * 32);
            ldsm4(B1, sb + bufo + kBrel + 2304 + ks * 32);
            mma168(acc[0][0], A0, B0[0], B0[2]); mma168(acc[0][1], A0, B0[1], B0[3]);
            mma168(acc[0][2], A0, B1[0], B1[2]); mma168(acc[0][3], A0, B1[1], B1[3]);
            mma168(acc[1][0], A1, B0[0], B0[2]); mma168(acc[1][1], A1, B0[1], B0[3]);
            mma168(acc[1][2], A1, B1[0], B1[2]); mma168(acc[1][3], A1, B1[1], B1[3]);
        }
        #pragma unroll
        for (int mi = 0; mi < 2; ++mi)
            #pragma unroll
            for (int nj = 0; nj < 4; ++nj) {
                float* p = o1 + (size_t)mi * 262144 + kt * 128 + nj * 8;
                st2(p,             __expf(acc[mi][nj][0]) * rv0[mi], __expf(acc[mi][nj][1]) * rv0[mi]);
                st2(p + 8 * 16384, __expf(acc[mi][nj][2]) * rv1[mi], __expf(acc[mi][nj][3]) * rv1[mi]);
            }
        __syncthreads();
    }
}

// =====================================================================
extern "C" void kernel_launch(void* const* d_in, const int* in_sizes, int n_in,
                              void* d_out, int out_size) {
    const float* q  = (const float*)d_in[0];
    const float* k  = (const float*)d_in[1];
    const float* Wq = (const float*)d_in[2];
    const float* bq = (const float*)d_in[3];
    const float* Wk = (const float*)d_in[4];
    const float* bk = (const float*)d_in[5];
    float* out = (float*)d_out;

    cudaFuncSetAttribute(hedgehog_main, cudaFuncAttributeMaxDynamicSharedMemorySize, SMEMB);
    hedgehog_prep2<<<512, 256>>>(q, k, Wq, bq, Wk, bk);
    hedgehog_ksum<<<512, 128>>>();
    hedgehog_main<<<dim3(8, 64), 512, SMEMB>>>(out);
}

// round 7
// speedup vs baseline: 5.1156x; 1.2490x over previous
#include <cuda_runtime.h>
#include <cuda_fp16.h>
#include <cstdint>

#define MAPSZ 67108864u
typedef unsigned uint;
typedef unsigned long long u64;

// ---------------- device scratch: single fp16 planes ----------------
__device__ __half g_q16[4194304];     // q * 0.125, [b][t][h][d]
__device__ __half g_k16[4194304];     // k,        [b][t][h][d]
__device__ __half g_pq16[8388608];    // phi_q,    [bh][t][128]
__device__ __half g_pk16[8388608];    // phi_k,    [bh][t][128]
__device__ float  g_skp[64 * 8 * 128];  // partial sums of phi_k

// ---------------- helpers ----------------
__device__ __forceinline__ float frcp(float x) { float r; asm("rcp.approx.ftz.f32 %0,%1;" : "=f"(r) : "f"(x)); return r; }
__device__ __forceinline__ uint packh(float hi, float lo) { uint r; asm("cvt.rn.f16x2.f32 %0,%1,%2;" : "=r"(r) : "f"(hi), "f"(lo)); return r; }
__device__ __forceinline__ uint smem_u32(const void* p) {
    uint a; asm("{ .reg .u64 t; cvta.to.shared.u64 t,%1; cvt.u32.u64 %0,t; }" : "=r"(a) : "l"(p)); return a;
}
__device__ __forceinline__ void cp16(uint dst, const void* src) {
    asm volatile("cp.async.cg.shared.global [%0],[%1],16;" :: "r"(dst), "l"(src));
}
#define CP_COMMIT() asm volatile("cp.async.commit_group;")
#define CP_WAIT0()  asm volatile("cp.async.wait_group 0;")
#define CP_WAIT1()  asm volatile("cp.async.wait_group 1;")

__device__ __forceinline__ void ldsm4(uint* r, uint addr) {
    asm volatile("ldmatrix.sync.aligned.m8n8.x4.shared.b16 {%0,%1,%2,%3},[%4];"
                 : "=r"(r[0]), "=r"(r[1]), "=r"(r[2]), "=r"(r[3]) : "r"(addr));
}
__device__ __forceinline__ void mma168(float* c, const uint* a, uint b0, uint b1) {
    asm volatile("mma.sync.aligned.m16n8k16.row.col.f32.f16.f16.f32 "
                 "{%0,%1,%2,%3},{%4,%5,%6,%7},{%8,%9},{%0,%1,%2,%3};"
                 : "+f"(c[0]), "+f"(c[1]), "+f"(c[2]), "+f"(c[3])
                 : "r"(a[0]), "r"(a[1]), "r"(a[2]), "r"(a[3]), "r"(b0), "r"(b1));
}
__device__ __forceinline__ void st2(float* p, float a, float b) {
    asm volatile("st.global.v2.f32 [%0],{%1,%2};" :: "l"(p), "f"(a), "f"(b) : "memory");
}

// =====================================================================
// Kernel 1: feature maps via hi/lo fp16 mma. grid 1024 = tensor(2) x b(4)
// x h(16) x tt(8); 256 threads (8 warps, one 16-row tile each).
// y = x @ W^T exact to ~2^-22; phi = [exp(y), 1/exp(y)] fp16.
// Also emits q16 (=q*0.125) / k16 planes.
// =====================================================================
#define PXH 0u
#define PXL 18432u
#define PWH 36864u
#define PWL 46080u
#define PREP_SMEM 55296

__global__ __launch_bounds__(256) void hedgehog_prep3(
    const float* __restrict__ q, const float* __restrict__ k,
    const float* __restrict__ Wq, const float* __restrict__ bq,
    const float* __restrict__ Wk, const float* __restrict__ bk)
{
    extern __shared__ __align__(16) char sm[];
    const uint sb = smem_u32(sm);
    const int tid = threadIdx.x, bid = blockIdx.x;
    const int w = tid >> 5, l = tid & 31;
    const int tensor = bid >> 9, rem = bid & 511;
    const int b = rem >> 7, h = (rem >> 3) & 15, t0 = (rem & 7) * 128;
    const float* W  = tensor ? Wk : Wq;
    const float* bi = tensor ? bk : bq;
    const float* x  = tensor ? k  : q;
    const float sc  = tensor ? 1.0f : 0.125f;
    __half* xout = tensor ? g_k16 : g_q16;
    __half* pout = tensor ? g_pk16 : g_pq16;

    // ---- stage W hi/lo: [e][d] stride 72h (B operand, row=n=e, col=k=d) ----
    #pragma unroll
    for (int i = 0; i < 16; ++i) {
        int idx = i * 256 + tid;
        int e = idx >> 6, d = idx & 63;
        float v = W[idx];
        __half hv = __float2half_rn(v);
        *(__half*)(sm + PWH + (e * 72 + d) * 2) = hv;
        *(__half*)(sm + PWL + (e * 72 + d) * 2) = __float2half_rn(v - __half2float(hv));
    }

    // ---- load x rows, emit q16/k16, stage Xh/Xl [t][d] stride 72h ----
    {
        const int row = tid >> 1, hf = tid & 1;
        const size_t xi = ((size_t)((b * 1024 + t0 + row) * 16 + h)) * 64 + hf * 32;
        const float4* xp = (const float4*)(x + xi);
        uint* xw = (uint*)(xout + xi);
        uint* XH = (uint*)(sm + PXH + (row * 72 + hf * 32) * 2);
        uint* XL = (uint*)(sm + PXL + (row * 72 + hf * 32) * 2);
        #pragma unroll
        for (int i = 0; i < 8; ++i) {
            float4 v = xp[i];
            xw[i * 2]     = packh(v.y * sc, v.x * sc);
            xw[i * 2 + 1] = packh(v.w * sc, v.z * sc);
            uint h0 = packh(v.y, v.x), h1 = packh(v.w, v.z);
            XH[i * 2] = h0; XH[i * 2 + 1] = h1;
            float2 r0 = __half22float2(*(__half2*)&h0), r1 = __half22float2(*(__half2*)&h1);
            XL[i * 2]     = packh(v.y - r0.y, v.x - r0.x);
            XL[i * 2 + 1] = packh(v.w - r1.y, v.z - r1.x);
        }
    }
    __syncthreads();

    // ---- MMA: warp w -> rows [w*16, w*16+16), all 64 outputs ----
    const uint aK  = (uint)(l >> 4) * 16;
    const uint aH  = sb + PXH + (w * 16 + (l & 15)) * 144u + aK;
    const uint aL  = sb + PXL + (w * 16 + (l & 15)) * 144u + aK;
    const uint bRow = (uint)((l & 7) + ((l >> 3) & 1) * 8);

    float acc[8][4];
    #pragma unroll
    for (int nj = 0; nj < 8; ++nj)
        #pragma unroll
        for (int e = 0; e < 4; ++e) acc[nj][e] = 0.f;

    #pragma unroll
    for (int ks = 0; ks < 4; ++ks) {
        uint AH[4], AL[4];
        ldsm4(AH, aH + ks * 32);
        ldsm4(AL, aL + ks * 32);
        #pragma unroll
        for (int g = 0; g < 4; ++g) {
            uint BH[4], BL[4];
            const uint bo = (g * 16 + bRow) * 144u + aK + ks * 32;
            ldsm4(BH, sb + PWH + bo);
            ldsm4(BL, sb + PWL + bo);
            mma168(acc[g * 2],     AH, BH[0], BH[2]);
            mma168(acc[g * 2],     AL, BH[0], BH[2]);
            mma168(acc[g * 2],     AH, BL[0], BL[2]);
            mma168(acc[g * 2 + 1], AH, BH[1], BH[3]);
            mma168(acc[g * 2 + 1], AL, BH[1], BH[3]);
            mma168(acc[g * 2 + 1], AH, BL[1], BL[3]);
        }
    }

    // ---- epilogue: bias, exp, rcp; write phi fp16 ----
    const float* bb = bi;  // bias in gmem (L2/const-cached; 8 scalar loads/thread)
    const int r0 = w * 16 + (l >> 2), r1 = r0 + 8;
    uint* p0 = (uint*)(pout + ((size_t)(b * 16 + h) * 1024 + t0 + r0) * 128);
    uint* p1 = (uint*)(pout + ((size_t)(b * 16 + h) * 1024 + t0 + r1) * 128);
    #pragma unroll
    for (int nj = 0; nj < 8; ++nj) {
        const int c = nj * 8 + (l & 3) * 2;
        const float b0 = bb[c], b1 = bb[c + 1];
        float e0 = __expf(acc[nj][0] + b0), e1 = __expf(acc[nj][1] + b1);
        float e2 = __expf(acc[nj][2] + b0), e3 = __expf(acc[nj][3] + b1);
        const int ci = nj * 4 + (l & 3);
        p0[ci]      = packh(e1, e0);
        p0[32 + ci] = packh(frcp(e1), frcp(e0));
        p1[ci]      = packh(e3, e2);
        p1[32 + ci] = packh(frcp(e3), frcp(e2));
    }
}

// =====================================================================
// Kernel 1b: partial column-sums of phi_k. grid 512 = bh(64) x chunk(8).
// =====================================================================
__global__ __launch_bounds__(128) void hedgehog_ksum() {
    const int blk = blockIdx.x, bh = blk >> 3, ch = blk & 7;
    const int e = threadIdx.x;
    const __half* src = g_pk16 + ((size_t)bh * 1024 + ch * 128) * 128 + e;
    float s = 0.f;
    #pragma unroll 4
    for (int t = 0; t < 128; ++t) s += __half2float(src[(size_t)t * 128]);
    g_skp[blk * 128 + e] = s;
}

// =====================================================================
// Kernel 2: fp16 mma.sync main. grid (8,64), 512 threads (16 warps 4x4).
// Sweep1: map1 rowsums (no store) + map2 store (normalized via inv2).
// Sweep2: map1 recompute + store normalized.
// =====================================================================
#define QOFF  0u
#define PQOFF 18432u
#define B0OFF 53248u
#define BSZ   53248u
#define SKOFF 159744u
#define IVOFF 160256u
#define RSOFF 160768u
#define SMEMB 161280

template<bool WITH_PK>
__device__ __forceinline__ void stageB(uint sb, uint bufo, int b, int h, int bh, int kr, int tid) {
    #pragma unroll
    for (int i = 0; i < 2; ++i) {
        int idx = i * 512 + tid;
        int r = idx >> 3, c = idx & 7;
        cp16(sb + bufo + r * 144u + c * 16u,
             g_k16 + ((size_t)((b * 1024 + kr + r) * 16 + h)) * 64 + c * 8);
    }
    if (WITH_PK) {
        #pragma unroll
        for (int i = 0; i < 4; ++i) {
            int idx = i * 512 + tid;
            int r = idx >> 4, c = idx & 15;
            cp16(sb + bufo + 18432u + r * 272u + c * 16u,
                 g_pk16 + ((size_t)bh * 1024 + kr + r) * 128 + c * 8);
        }
    }
}

__global__ __launch_bounds__(512, 1) void hedgehog_main(float* __restrict__ out)
{
    extern __shared__ __align__(16) char sm[];
    const uint sb = smem_u32(sm);
    const int tid = threadIdx.x, w = tid >> 5, l = tid & 31;
    const int wr = w >> 2, wc = w & 3;
    const int qt = blockIdx.x, bh = blockIdx.y;
    const int b = bh >> 4, h = bh & 15, t0 = qt * 128;
    float* skf = (float*)(sm + SKOFF);
    float* ivf = (float*)(sm + IVOFF);
    float* rsf = (float*)(sm + RSOFF);

    #pragma unroll
    for (int i = 0; i < 2; ++i) {
        int idx = i * 512 + tid;
        int r = idx >> 3, c = idx & 7;
        cp16(sb + QOFF + r * 144u + c * 16u,
             g_q16 + ((size_t)((b * 1024 + t0 + r) * 16 + h)) * 64 + c * 8);
    }
    #pragma unroll
    for (int i = 0; i < 4; ++i) {
        int idx = i * 512 + tid;
        int r = idx >> 4, c = idx & 15;
        cp16(sb + PQOFF + r * 272u + c * 16u,
             g_pq16 + ((size_t)bh * 1024 + t0 + r) * 128 + c * 8);
    }
    stageB<true>(sb, B0OFF, b, h, bh, 0, tid);
    CP_COMMIT();

    if (tid < 128) {
        float s = 0.f;
        #pragma unroll
        for (int c = 0; c < 8; ++c) s += g_skp[(bh * 8 + c) * 128 + tid];
        skf[tid] = s;
        rsf[tid] = 0.f;
    }
    CP_WAIT0();
    __syncthreads();

    if (tid < 128) {
        const uint* pr = (const uint*)(sm + PQOFF + tid * 272);
        float s = 0.f;
        #pragma unroll 16
        for (int i = 0; i < 64; ++i) {
            float2 v = __half22float2(*(const __half2*)(pr + i));
            s = fmaf(v.x, skf[2 * i], s);
            s = fmaf(v.y, skf[2 * i + 1], s);
        }
        ivf[tid] = 1.0f / s;
    }
    __syncthreads();

    const uint aK = (uint)(l >> 4) * 16;
    const uint qA = sb + QOFF  + (wr * 32 + (l & 15)) * 144u + aK;
    const uint pA = sb + PQOFF + (wr * 32 + (l & 15)) * 272u + aK;
    const uint bRow = (uint)((l & 7) + ((l >> 3) & 1) * 8);
    const uint kBrel = (wc * 32 + bRow) * 144u + aK;
    const uint pBrel = (wc * 32 + bRow) * 272u + aK + 18432u;

    float* o1 = out + ((size_t)((b * 1024 + t0 + wr * 32 + (l >> 2)) * 16 + h)) * 1024
                + wc * 32 + 2 * (l & 3);
    float* o2 = o1 + MAPSZ;

    float iv0[2], iv1[2];
    #pragma unroll
    for (int mi = 0; mi < 2; ++mi) {
        iv0[mi] = ivf[wr * 32 + mi * 16 + (l >> 2)];
        iv1[mi] = ivf[wr * 32 + mi * 16 + (l >> 2) + 8];
    }
    float rlo[2] = {0.f, 0.f}, rhi[2] = {0.f, 0.f};

    // ================= sweep 1 =================
    for (int kt = 0; kt < 8; ++kt) {
        if (kt < 7) { stageB<true>(sb, B0OFF + ((kt + 1) & 1) * BSZ, b, h, bh, (kt + 1) * 128, tid); CP_COMMIT(); CP_WAIT1(); }
        else CP_WAIT0();
        __syncthreads();
        const uint bufo = B0OFF + (kt & 1) * BSZ;

        float acc[2][4][4];
        #pragma unroll
        for (int mi = 0; mi < 2; ++mi)
            #pragma unroll
            for (int nj = 0; nj < 4; ++nj)
                #pragma unroll
                for (int e = 0; e < 4; ++e) acc[mi][nj][e] = 0.f;
        #pragma unroll
        for (int ks = 0; ks < 4; ++ks) {
            uint A0[4], A1[4], B0[4], B1[4];
            ldsm4(A0, qA + ks * 32);
            ldsm4(A1, qA + 2304 + ks * 32);
            ldsm4(B0, sb + bufo + kBrel + ks * 32);
            ldsm4(B1, sb + bufo + kBrel + 2304 + ks * 32);
            mma168(acc[0][0], A0, B0[0], B0[2]); mma168(acc[0][1], A0, B0[1], B0[3]);
            mma168(acc[0][2], A0, B1[0], B1[2]); mma168(acc[0][3], A0, B1[1], B1[3]);
            mma168(acc[1][0], A1, B0[0], B0[2]); mma168(acc[1][1], A1, B0[1], B0[3]);
            mma168(acc[1][2], A1, B1[0], B1[2]); mma168(acc[1][3], A1, B1[1], B1[3]);
        }
        #pragma unroll
        for (int mi = 0; mi < 2; ++mi)
            #pragma unroll
            for (int nj = 0; nj < 4; ++nj) {
                rlo[mi] += __expf(acc[mi][nj][0]) + __expf(acc[mi][nj][1]);
                rhi[mi] += __expf(acc[mi][nj][2]) + __expf(acc[mi][nj][3]);
            }

        #pragma unroll
        for (int mi = 0; mi < 2; ++mi)
            #pragma unroll
            for (int nj = 0; nj < 4; ++nj)
                #pragma unroll
                for (int e = 0; e < 4; ++e) acc[mi][nj][e] = 0.f;
        #pragma unroll
        for (int ks = 0; ks < 8; ++ks) {
            uint A0[4], A1[4], B0[4], B1[4];
            ldsm4(A0, pA + ks * 32);
            ldsm4(A1, pA + 4352 + ks * 32);
            ldsm4(B0, sb + bufo + pBrel + ks * 32);
            ldsm4(B1, sb + bufo + pBrel + 4352 + ks * 32);
            mma168(acc[0][0], A0, B0[0], B0[2]); mma168(acc[0][1], A0, B0[1], B0[3]);
            mma168(acc[0][2], A0, B1[0], B1[2]); mma168(acc[0][3], A0, B1[1], B1[3]);
            mma168(acc[1][0], A1, B0[0], B0[2]); mma168(acc[1][1], A1, B0[1], B0[3]);
            mma168(acc[1][2], A1, B1[0], B1[2]); mma168(acc[1][3], A1, B1[1], B1[3]);
        }
        #pragma unroll
        for (int mi = 0; mi < 2; ++mi)
            #pragma unroll
            for (int nj = 0; nj < 4; ++nj) {
                float* p = o2 + (size_t)mi * 262144 + kt * 128 + nj * 8;
                st2(p,             acc[mi][nj][0] * iv0[mi], acc[mi][nj][1] * iv0[mi]);
                st2(p + 8 * 16384, acc[mi][nj][2] * iv1[mi], acc[mi][nj][3] * iv1[mi]);
            }
        __syncthreads();
    }

    #pragma unroll
    for (int mi = 0; mi < 2; ++mi) {
        rlo[mi] += __shfl_xor_sync(0xffffffffu, rlo[mi], 1);
        rlo[mi] += __shfl_xor_sync(0xffffffffu, rlo[mi], 2);
        rhi[mi] += __shfl_xor_sync(0xffffffffu, rhi[mi], 1);
        rhi[mi] += __shfl_xor_sync(0xffffffffu, rhi[mi], 2);
        if ((l & 3) == 0) {
            atomicAdd(&rsf[wr * 32 + mi * 16 + (l >> 2)], rlo[mi]);
            atomicAdd(&rsf[wr * 32 + mi * 16 + (l >> 2) + 8], rhi[mi]);
        }
    }
    __syncthreads();
    if (tid < 128) rsf[tid] = 1.0f / rsf[tid];
    __syncthreads();

    float rv0[2], rv1[2];
    #pragma unroll
    for (int mi = 0; mi < 2; ++mi) {
        rv0[mi] = rsf[wr * 32 + mi * 16 + (l >> 2)];
        rv1[mi] = rsf[wr * 32 + mi * 16 + (l >> 2) + 8];
    }

    // ================= sweep 2 =================
    stageB<false>(sb, B0OFF, b, h, bh, 0, tid);
    CP_COMMIT();
    for (int kt = 0; kt < 8; ++kt) {
        if (kt < 7) { stageB<false>(sb, B0OFF + ((kt + 1) & 1) * BSZ, b, h, bh, (kt + 1) * 128, tid); CP_COMMIT(); CP_WAIT1(); }
        else CP_WAIT0();
        __syncthreads();
        const uint bufo = B0OFF + (kt & 1) * BSZ;

        float acc[2][4][4];
        #pragma unroll
        for (int mi = 0; mi < 2; ++mi)
            #pragma unroll
            for (int nj = 0; nj < 4; ++nj)
                #pragma unroll
                for (int e = 0; e < 4; ++e) acc[mi][nj][e] = 0.f;
        #pragma unroll
        for (int ks = 0; ks < 4; ++ks) {
            uint A0[4], A1[4], B0[4], B1[4];
            ldsm4(A0, qA + ks * 32);
            ldsm4(A1, qA + 2304 + ks * 32);
            ldsm4(B0, sb + bufo + kBrel + ks * 32);
            ldsm4(B1, sb + bufo + kBrel + 2304 + ks * 32);
            mma168(acc[0][0], A0, B0[0], B0[2]); mma168(acc[0][1], A0, B0[1], B0[3]);
            mma168(acc[0][2], A0, B1[0], B1[2]); mma168(acc[0][3], A0, B1[1], B1[3]);
            mma168(acc[1][0], A1, B0[0], B0[2]); mma168(acc[1][1], A1, B0[1], B0[3]);
            mma168(acc[1][2], A1, B1[0], B1[2]); mma168(acc[1][3], A1, B1[1], B1[3]);
        }
        #pragma unroll
        for (int mi = 0; mi < 2; ++mi)
            #pragma unroll
            for (int nj = 0; nj < 4; ++nj) {
                float* p = o1 + (size_t)mi * 262144 + kt * 128 + nj * 8;
                st2(p,             __expf(acc[mi][nj][0]) * rv0[mi], __expf(acc[mi][nj][1]) * rv0[mi]);
                st2(p + 8 * 16384, __expf(acc[mi][nj][2]) * rv1[mi], __expf(acc[mi][nj][3]) * rv1[mi]);
            }
        __syncthreads();
    }
}

// =====================================================================
extern "C" void kernel_launch(void* const* d_in, const int* in_sizes, int n_in,
                              void* d_out, int out_size) {
    const float* q  = (const float*)d_in[0];
    const float* k  = (const float*)d_in[1];
    const float* Wq = (const float*)d_in[2];
    const float* bq = (const float*)d_in[3];
    const float* Wk = (const float*)d_in[4];
    const float* bk = (const float*)d_in[5];
    float* out = (float*)d_out;

    cudaFuncSetAttribute(hedgehog_prep3, cudaFuncAttributeMaxDynamicSharedMemorySize, PREP_SMEM);
    cudaFuncSetAttribute(hedgehog_main, cudaFuncAttributeMaxDynamicSharedMemorySize, SMEMB);
    hedgehog_prep3<<<1024, 256, PREP_SMEM>>>(q, k, Wq, bq, Wk, bk);
    hedgehog_ksum<<<512, 128>>>();
    hedgehog_main<<<dim3(8, 64), 512, SMEMB>>>(out);
}